// round 9
// baseline (speedup 1.0000x reference)
#include <cuda_runtime.h>
#include <cuda_fp16.h>
#include <cstdint>
#include <math.h>

// Problem constants
#define BB 2
#define SS 2048
#define DD 768
#define NH 12
#define DK 64
#define DV 64
#define GG 1
#define NIDX 6
#define SMID (SS - 2*GG)
#define MROWS (BB * SS)

// GEMM tiling
#define BM 128
#define BKK 32                    // f16 K elems per stage
#define NCHK (DD / BKK)           // 24 k-iterations
#define LDT 40                    // padded row stride (elements): 80B
#define NSTG 2

// Fused attention kernel geometry
#define MID_WPB 8
#define N_ITEMS (BB * NH * SMID)                  // 49104
#define NBLK_MID ((N_ITEMS + MID_WPB - 1) / MID_WPB)   // 6138
#define NBLK_GLB (BB * NH * 2)                    // 48

// ---------------------------------------------------------------------------
// Scratch
// ---------------------------------------------------------------------------
__device__ float g_v[MROWS * DD];
__device__ float g_vsum[BB * DD];

__device__ __half g_qp[MROWS * DD];          // projected q (f16)
__device__ __half g_kp[MROWS * DD];          // projected k (f16)
__device__ __half g_qh[MROWS * DD];          // input Q hi
__device__ __half g_kh[MROWS * DD];          // input K hi
__device__ __half g_vh[MROWS * DD], g_vl[MROWS * DD];
__device__ __half g_ah[MROWS * DD], g_al[MROWS * DD];
__device__ __half g_wqh[DD * DD];
__device__ __half g_wkh[DD * DD];
__device__ __half g_wvh[DD * DD], g_wvl[DD * DD];
__device__ __half g_woh[DD * DD], g_wol[DD * DD];

// ---------------------------------------------------------------------------
// PTX helpers (portable sm_80+ ISA)
// ---------------------------------------------------------------------------
__device__ __forceinline__ uint32_t smem_u32(const void* p) {
    uint32_t a;
    asm("{ .reg .u64 t; cvta.to.shared.u64 t, %1; cvt.u32.u64 %0, t; }"
        : "=r"(a) : "l"(p));
    return a;
}
__device__ __forceinline__ void cp_async16(uint32_t dst, const void* src) {
    asm volatile("cp.async.cg.shared.global [%0], [%1], 16;"
                 :: "r"(dst), "l"(src) : "memory");
}
__device__ __forceinline__ void cp_commit() {
    asm volatile("cp.async.commit_group;" ::: "memory");
}
template <int N>
__device__ __forceinline__ void cp_wait() {
    asm volatile("cp.async.wait_group %0;" :: "n"(N) : "memory");
}
__device__ __forceinline__ void ldm4(uint32_t* r, uint32_t addr) {
    asm volatile("ldmatrix.sync.aligned.m8n8.x4.shared.b16 {%0,%1,%2,%3}, [%4];"
                 : "=r"(r[0]), "=r"(r[1]), "=r"(r[2]), "=r"(r[3]) : "r"(addr));
}
__device__ __forceinline__ void mma16816(float* c, const uint32_t* a, const uint32_t* b) {
    asm volatile(
        "mma.sync.aligned.m16n8k16.row.col.f32.f16.f16.f32 "
        "{%0,%1,%2,%3}, {%4,%5,%6,%7}, {%8,%9}, {%0,%1,%2,%3};"
        : "+f"(c[0]), "+f"(c[1]), "+f"(c[2]), "+f"(c[3])
        : "r"(a[0]), "r"(a[1]), "r"(a[2]), "r"(a[3]), "r"(b[0]), "r"(b[1]));
}

struct GemmArgs {
    const __half *Ah, *Al, *Bh, *Bl;
    float* C;         // fp32 output (used when Ch == nullptr)
    __half* Ch;       // f16 output (q/k projections)
    float* vsum;      // non-null: accumulate per-batch column sums (V GEMM)
    int nprod;        // 1: Ah*Bh ; 3: Ah*Bh + Ah*Bl + Al*Bh
};
struct Gemm3 { GemmArgs g[3]; };

// ---------------------------------------------------------------------------
// C[M,768] = Ah*Bh^T (+ Ah*Bl^T + Al*Bh^T)   f16 split-fp32, B is [768,768]
// Template on BNT (CTA N-tile). 8 warps, 2m x 4n layout, NSTG=2, 2 CTAs/SM.
// ---------------------------------------------------------------------------
template <int BNT>
__global__ __launch_bounds__(256, 2) void gemm_mma(Gemm3 ga)
{
    constexpr int WNT = BNT / 4;                 // warp n-tile (32 or 16)
    constexpr int NJ = WNT / 8;                  // n8 tiles per warp (4 or 2)
    constexpr int TILEB_A = 128 * LDT * 2;       // 10240
    constexpr int TILEB_B = BNT * LDT * 2;
    constexpr int STAGEB = 2 * TILEB_A + 2 * TILEB_B;
    constexpr int NCHUNK = (2 * 128 + 2 * BNT) * 4;   // 16B chunks per stage
    constexpr int PER_THR = NCHUNK / 256;

    extern __shared__ char smem[];
    const GemmArgs& A = ga.g[blockIdx.z];
    const int nprod = A.nprod;
    const uint32_t sb = smem_u32(smem);
    const int tid = threadIdx.x;
    const int wid = tid >> 5;
    const int lane = tid & 31;
    const int bm = blockIdx.y * BM;
    const int bn = blockIdx.x * BNT;
    const int wm = (wid >> 2) * 64;
    const int wn = (wid & 3) * WNT;

    float acc[4][NJ][4];
    #pragma unroll
    for (int i = 0; i < 4; i++)
        #pragma unroll
        for (int j = 0; j < NJ; j++)
            #pragma unroll
            for (int e = 0; e < 4; e++) acc[i][j][e] = 0.0f;

    // chunk layout: [Ah(512) | Al(512) | Bh(BNT*4) | Bl(BNT*4)]
    auto issue = [&](int kt) {
        const int st = kt % NSTG;
        #pragma unroll
        for (int q8 = 0; q8 < PER_THR; q8++) {
            int q = tid + q8 * 256;
            if (q < 1024) {
                int t = q >> 9;                  // 0=Ah 1=Al
                if (t == 1 && nprod < 3) continue;
                int r = (q >> 2) & 127;
                int c = q & 3;
                const __half* src = (t ? A.Al : A.Ah)
                                    + (size_t)(bm + r) * DD + kt * BKK + c * 8;
                uint32_t dst = sb + st * STAGEB + t * TILEB_A + r * (LDT * 2) + c * 16;
                cp_async16(dst, src);
            } else {
                int q2 = q - 1024;
                int t = q2 / (BNT * 4);          // 0=Bh 1=Bl
                if (t == 1 && nprod < 2) continue;
                int r = (q2 >> 2) % BNT;
                int c = q2 & 3;
                const __half* src = (t ? A.Bl : A.Bh)
                                    + (size_t)(bn + r) * DD + kt * BKK + c * 8;
                uint32_t dst = sb + st * STAGEB + 2 * TILEB_A + t * TILEB_B
                             + r * (LDT * 2) + c * 16;
                cp_async16(dst, src);
            }
        }
        cp_commit();
    };

    const int a_row = lane & 15;
    const int a_col = (lane >> 4) * 8;
    const int b_row = (lane & 7) + ((lane >> 4) << 3);
    const int b_col = ((lane >> 3) & 1) * 8;

    auto compute = [&](int kt) {
        const uint32_t base = sb + (kt % NSTG) * STAGEB;
        #pragma unroll
        for (int ks = 0; ks < 2; ks++) {
            const int k0 = ks * 16;
            uint32_t bh[NJ / 2][4], bl[NJ / 2][4];
            #pragma unroll
            for (int nh = 0; nh < NJ / 2; nh++) {
                uint32_t off = (uint32_t)(wn + nh * 16 + b_row) * (LDT * 2)
                             + (k0 + b_col) * 2;
                ldm4(bh[nh], base + 2 * TILEB_A + off);
                if (nprod >= 2)
                    ldm4(bl[nh], base + 2 * TILEB_A + TILEB_B + off);
            }
            uint32_t af[4][4];
            #pragma unroll
            for (int mt = 0; mt < 4; mt++) {
                uint32_t off = (uint32_t)(wm + mt * 16 + a_row) * (LDT * 2)
                             + (k0 + a_col) * 2;
                ldm4(af[mt], base + off);
            }
            if constexpr (NJ == 2) {
                // Registers allow holding A-lo alongside: fully pipelined 3rd product.
                uint32_t alf[4][4];
                if (nprod >= 3) {
                    #pragma unroll
                    for (int mt = 0; mt < 4; mt++) {
                        uint32_t off = (uint32_t)(wm + mt * 16 + a_row) * (LDT * 2)
                                     + (k0 + a_col) * 2;
                        ldm4(alf[mt], base + TILEB_A + off);
                    }
                }
                #pragma unroll
                for (int mt = 0; mt < 4; mt++)
                    #pragma unroll
                    for (int j = 0; j < NJ; j++) {
                        mma16816(acc[mt][j], af[mt], &bh[j >> 1][(j & 1) * 2]);
                        if (nprod >= 2)
                            mma16816(acc[mt][j], af[mt], &bl[j >> 1][(j & 1) * 2]);
                        if (nprod >= 3)
                            mma16816(acc[mt][j], alf[mt], &bh[j >> 1][(j & 1) * 2]);
                    }
            } else {
                #pragma unroll
                for (int mt = 0; mt < 4; mt++)
                    #pragma unroll
                    for (int j = 0; j < NJ; j++) {
                        mma16816(acc[mt][j], af[mt], &bh[j >> 1][(j & 1) * 2]);
                        if (nprod >= 2)
                            mma16816(acc[mt][j], af[mt], &bl[j >> 1][(j & 1) * 2]);
                    }
                if (nprod >= 3) {   // third product: Al * Bh (reload af with A-lo)
                    #pragma unroll
                    for (int mt = 0; mt < 4; mt++) {
                        uint32_t off = (uint32_t)(wm + mt * 16 + a_row) * (LDT * 2)
                                     + (k0 + a_col) * 2;
                        ldm4(af[mt], base + TILEB_A + off);
                    }
                    #pragma unroll
                    for (int mt = 0; mt < 4; mt++)
                        #pragma unroll
                        for (int j = 0; j < NJ; j++)
                            mma16816(acc[mt][j], af[mt], &bh[j >> 1][(j & 1) * 2]);
                }
            }
        }
    };

    issue(0);
    for (int kt = 0; kt < NCHK; kt++) {
        cp_wait<0>();
        __syncthreads();
        if (kt + 1 < NCHK) issue(kt + 1);
        compute(kt);
    }

    if (A.Ch) {   // f16 output (q/k projections)
        #pragma unroll
        for (int mt = 0; mt < 4; mt++) {
            #pragma unroll
            for (int j = 0; j < NJ; j++) {
                int row = bm + wm + mt * 16 + (lane >> 2);
                int col = bn + wn + j * 8 + (lane & 3) * 2;
                *reinterpret_cast<__half2*>(A.Ch + (size_t)row * DD + col)
                    = __floats2half2_rn(acc[mt][j][0], acc[mt][j][1]);
                *reinterpret_cast<__half2*>(A.Ch + (size_t)(row + 8) * DD + col)
                    = __floats2half2_rn(acc[mt][j][2], acc[mt][j][3]);
            }
        }
    } else {
        #pragma unroll
        for (int mt = 0; mt < 4; mt++) {
            #pragma unroll
            for (int j = 0; j < NJ; j++) {
                int row = bm + wm + mt * 16 + (lane >> 2);
                int col = bn + wn + j * 8 + (lane & 3) * 2;
                *reinterpret_cast<float2*>(A.C + (size_t)row * DD + col)
                    = make_float2(acc[mt][j][0], acc[mt][j][1]);
                *reinterpret_cast<float2*>(A.C + (size_t)(row + 8) * DD + col)
                    = make_float2(acc[mt][j][2], acc[mt][j][3]);
            }
        }
    }

    // Fused per-batch column sums (V GEMM only)
    if (A.vsum) {
        int b = bm / SS;
        #pragma unroll
        for (int j = 0; j < NJ; j++) {
            float s0 = 0.0f, s1 = 0.0f;
            #pragma unroll
            for (int mt = 0; mt < 4; mt++) {
                s0 += acc[mt][j][0] + acc[mt][j][2];
                s1 += acc[mt][j][1] + acc[mt][j][3];
            }
            #pragma unroll
            for (int o = 4; o < 32; o <<= 1) {
                s0 += __shfl_xor_sync(0xFFFFFFFFu, s0, o);
                s1 += __shfl_xor_sync(0xFFFFFFFFu, s1, o);
            }
            if (lane < 4) {
                int col = bn + wn + j * 8 + lane * 2;
                atomicAdd(&A.vsum[b * DD + col], s0);
                atomicAdd(&A.vsum[b * DD + col + 1], s1);
            }
        }
    }
}

// ---------------------------------------------------------------------------
// fp32 -> (f16 hi, f16 lo) splits; lo pointer may be null.
// Weight variant also zeroes g_vsum.
// ---------------------------------------------------------------------------
__device__ __forceinline__ void split4h(float4 v, ushort4& h, ushort4& l) {
    __half b;
    b = __float2half(v.x); h.x = __half_as_ushort(b);
    l.x = __half_as_ushort(__float2half(v.x - __half2float(b)));
    b = __float2half(v.y); h.y = __half_as_ushort(b);
    l.y = __half_as_ushort(__float2half(v.y - __half2float(b)));
    b = __float2half(v.z); h.z = __half_as_ushort(b);
    l.z = __half_as_ushort(__float2half(v.z - __half2float(b)));
    b = __float2half(v.w); h.w = __half_as_ushort(b);
    l.w = __half_as_ushort(__float2half(v.w - __half2float(b)));
}

struct SplitN {
    const float4* x[4];
    ushort4* hi[4];
    ushort4* lo[4];
    int zero_vsum;
};
__global__ void split_multi(SplitN a, int n4)
{
    int w = blockIdx.y;
    int i = blockIdx.x * blockDim.x + threadIdx.x;
    if (a.zero_vsum && w == 0 && i < BB * DD) g_vsum[i] = 0.0f;
    if (i >= n4) return;
    ushort4 h, l;
    split4h(a.x[w][i], h, l);
    a.hi[w][i] = h;
    if (a.lo[w]) a.lo[w][i] = l;
}

// ---------------------------------------------------------------------------
// Fused attention kernel: blocks [0,NBLK_MID) do middle rows (1 warp/item);
// blocks [NBLK_MID, NBLK_MID+NBLK_GLB) do full-softmax global rows.
// ---------------------------------------------------------------------------
__device__ __forceinline__ void store_hl(size_t off, float v) {
    __half h = __float2half(v);
    g_ah[off] = h;
    g_al[off] = __float2half(v - __half2float(h));
}

__global__ __launch_bounds__(256) void attn_kernel(const int* __restrict__ idx)
{
    if (blockIdx.x < NBLK_MID) {
        // ------------------- middle rows -------------------
        int item = blockIdx.x * MID_WPB + (threadIdx.x >> 5);
        if (item >= N_ITEMS) return;
        int lane = threadIdx.x & 31;

        int i = item % SMID;
        int h = (item / SMID) % NH;
        int b = item / (SMID * NH);
        int s = i + GG;

        const __half* qrow = g_qp + ((size_t)b * SS + s) * DD + h * DK;
        float q0 = __half2float(qrow[lane]);
        float q1 = __half2float(qrow[lane + 32]);

        int cols[NIDX];
        #pragma unroll
        for (int j = 0; j < NIDX; j++) cols[j] = idx[i * NIDX + j];

        // issue ALL k and v loads up front (single latency round)
        float k0v[NIDX], k1v[NIDX], v0[NIDX], v1[NIDX];
        #pragma unroll
        for (int j = 0; j < NIDX; j++) {
            const __half* krow = g_kp + ((size_t)b * SS + cols[j]) * DD + h * DK;
            const float* vrow = g_v + ((size_t)b * SS + cols[j]) * DD + h * DV;
            k0v[j] = __half2float(krow[lane]);
            k1v[j] = __half2float(krow[lane + 32]);
            v0[j] = vrow[lane];
            v1[j] = vrow[lane + 32];
        }

        float sc[NIDX];
        #pragma unroll
        for (int j = 0; j < NIDX; j++) {
            float p = q0 * k0v[j] + q1 * k1v[j];
            #pragma unroll
            for (int o = 16; o > 0; o >>= 1) p += __shfl_xor_sync(0xFFFFFFFFu, p, o);
            sc[j] = p;
        }

        float wgt[NIDX];
        float denom = (float)SS;
        #pragma unroll
        for (int j = 0; j < NIDX; j++) {
            bool dup = false;
            #pragma unroll
            for (int jj = 0; jj < NIDX; jj++)
                if (jj < j) dup = dup || (cols[jj] == cols[j]);
            float w = dup ? 0.0f : (expf(sc[j] * 0.125f) - 1.0f);
            wgt[j] = w;
            denom += w;
        }

        const float* vs = g_vsum + b * DD + h * DV;
        float o0 = vs[lane];
        float o1 = vs[lane + 32];
        #pragma unroll
        for (int j = 0; j < NIDX; j++) {
            o0 = fmaf(wgt[j], v0[j], o0);
            o1 = fmaf(wgt[j], v1[j], o1);
        }
        float inv = 1.0f / denom;
        size_t base = ((size_t)b * SS + s) * DD + h * DV;
        store_hl(base + lane, o0 * inv);
        store_hl(base + lane + 32, o1 * inv);
    } else {
        // ------------------- global rows -------------------
        int item = blockIdx.x - NBLK_MID;
        int r = item % 2;
        int h = (item / 2) % NH;
        int b = item / (2 * NH);
        int s = r ? (SS - 1) : 0;
        int tid = threadIdx.x;

        __shared__ float sc[SS];
        __shared__ float qs[DK];
        __shared__ float red[256];

        const __half* qrow = g_qp + ((size_t)b * SS + s) * DD + h * DK;
        if (tid < DK) qs[tid] = __half2float(qrow[tid]);
        __syncthreads();

        for (int t = tid; t < SS; t += 256) {
            const __half* krow = g_kp + ((size_t)b * SS + t) * DD + h * DK;
            float p = 0.0f;
            #pragma unroll
            for (int d = 0; d < DK; d++) p = fmaf(qs[d], __half2float(krow[d]), p);
            sc[t] = p * 0.125f;
        }
        __syncthreads();

        float m = -1e30f;
        for (int t = tid; t < SS; t += 256) m = fmaxf(m, sc[t]);
        red[tid] = m; __syncthreads();
        for (int o = 128; o > 0; o >>= 1) {
            if (tid < o) red[tid] = fmaxf(red[tid], red[tid + o]);
            __syncthreads();
        }
        m = red[0];
        __syncthreads();

        float sum = 0.0f;
        for (int t = tid; t < SS; t += 256) {
            float e = expf(sc[t] - m);
            sc[t] = e;
            sum += e;
        }
        red[tid] = sum; __syncthreads();
        for (int o = 128; o > 0; o >>= 1) {
            if (tid < o) red[tid] += red[tid + o];
            __syncthreads();
        }
        float inv = 1.0f / red[0];
        __syncthreads();

        int dv = tid % DV;
        int chunk = tid / DV;
        float acc = 0.0f;
        const float* vb = g_v + (size_t)b * SS * DD + h * DV + dv;
        for (int t = chunk * (SS / 4); t < (chunk + 1) * (SS / 4); t++)
            acc = fmaf(sc[t], vb[(size_t)t * DD], acc);
        red[tid] = acc; __syncthreads();
        if (tid < DV) {
            float o = (red[dv] + red[DV + dv] + red[2 * DV + dv] + red[3 * DV + dv]) * inv;
            store_hl(((size_t)b * SS + s) * DD + h * DV + dv, o);
        }
    }
}

// ---------------------------------------------------------------------------
extern "C" void kernel_launch(void* const* d_in, const int* in_sizes, int n_in,
                              void* d_out, int out_size)
{
    const float* Q  = (const float*)d_in[0];
    const float* K  = (const float*)d_in[1];
    const float* V  = (const float*)d_in[2];
    const float* Wq = (const float*)d_in[3];
    const float* Wk = (const float*)d_in[4];
    const float* Wv = (const float*)d_in[5];
    const float* Wo = (const float*)d_in[6];
    const int*   idx = (const int*)d_in[7];
    float* out = (float*)d_out;

    float *pv, *pvs;
    cudaGetSymbolAddress((void**)&pv, g_v);
    cudaGetSymbolAddress((void**)&pvs, g_vsum);

    __half *qp, *kp, *qh, *kh, *vh, *vl, *ah, *al;
    __half *wqh, *wkh, *wvh, *wvl, *woh, *wol;
    cudaGetSymbolAddress((void**)&qp, g_qp);
    cudaGetSymbolAddress((void**)&kp, g_kp);
    cudaGetSymbolAddress((void**)&qh, g_qh);
    cudaGetSymbolAddress((void**)&kh, g_kh);
    cudaGetSymbolAddress((void**)&vh, g_vh);  cudaGetSymbolAddress((void**)&vl, g_vl);
    cudaGetSymbolAddress((void**)&ah, g_ah);  cudaGetSymbolAddress((void**)&al, g_al);
    cudaGetSymbolAddress((void**)&wqh, g_wqh);
    cudaGetSymbolAddress((void**)&wkh, g_wkh);
    cudaGetSymbolAddress((void**)&wvh, g_wvh); cudaGetSymbolAddress((void**)&wvl, g_wvl);
    cudaGetSymbolAddress((void**)&woh, g_woh); cudaGetSymbolAddress((void**)&wol, g_wol);

    constexpr int SMEM128 = NSTG * (2 * 128 * LDT * 2 + 2 * 128 * LDT * 2); // 81920
    constexpr int SMEM64  = NSTG * (2 * 128 * LDT * 2 + 2 * 64 * LDT * 2);  // 61440
    cudaFuncSetAttribute(gemm_mma<128>, cudaFuncAttributeMaxDynamicSharedMemorySize, SMEM128);
    cudaFuncSetAttribute(gemm_mma<64>,  cudaFuncAttributeMaxDynamicSharedMemorySize, SMEM64);

    const int n4_big = MROWS * DD / 4;
    const int n4_w   = DD * DD / 4;
    const int bl_big = (n4_big + 255) / 256;
    const int bl_w   = (n4_w + 255) / 256;

    SplitN si;
    si.x[0] = (const float4*)Q; si.hi[0] = (ushort4*)qh; si.lo[0] = nullptr;
    si.x[1] = (const float4*)K; si.hi[1] = (ushort4*)kh; si.lo[1] = nullptr;
    si.x[2] = (const float4*)V; si.hi[2] = (ushort4*)vh; si.lo[2] = (ushort4*)vl;
    si.x[3] = si.x[0]; si.hi[3] = si.hi[0]; si.lo[3] = nullptr;
    si.zero_vsum = 0;
    split_multi<<<dim3(bl_big, 3), 256>>>(si, n4_big);

    SplitN sw;
    sw.x[0] = (const float4*)Wq; sw.hi[0] = (ushort4*)wqh; sw.lo[0] = nullptr;
    sw.x[1] = (const float4*)Wk; sw.hi[1] = (ushort4*)wkh; sw.lo[1] = nullptr;
    sw.x[2] = (const float4*)Wv; sw.hi[2] = (ushort4*)wvh; sw.lo[2] = (ushort4*)wvl;
    sw.x[3] = (const float4*)Wo; sw.hi[3] = (ushort4*)woh; sw.lo[3] = (ushort4*)wol;
    sw.zero_vsum = 1;
    split_multi<<<dim3(bl_w, 4), 256>>>(sw, n4_w);

    Gemm3 g3;
    g3.g[0] = {qh, nullptr, wqh, nullptr, nullptr, qp, nullptr, 1};
    g3.g[1] = {kh, nullptr, wkh, nullptr, nullptr, kp, nullptr, 1};
    g3.g[2] = {vh, vl,      wvh, wvl,     pv,      nullptr, pvs, 3};
    gemm_mma<128><<<dim3(DD / 128, MROWS / BM, 3), 256, SMEM128>>>(g3);

    attn_kernel<<<NBLK_MID + NBLK_GLB, 256>>>(idx);

    Gemm3 go;
    go.g[0] = {ah, al, woh, wol, out, nullptr, nullptr, 3};
    go.g[1] = go.g[0];
    go.g[2] = go.g[0];
    gemm_mma<64><<<dim3(DD / 64, MROWS / BM, 1), 256, SMEM64>>>(go);
}

// round 10
// speedup vs baseline: 1.0603x; 1.0603x over previous
#include <cuda_runtime.h>
#include <cuda_fp16.h>
#include <cstdint>
#include <math.h>

// Problem constants
#define BB 2
#define SS 2048
#define DD 768
#define NH 12
#define DK 64
#define DV 64
#define GG 1
#define NIDX 6
#define SMID (SS - 2*GG)
#define MROWS (BB * SS)

// GEMM tiling
#define BM 128
#define BKK 32
#define NCHK (DD / BKK)
#define LDT 40
#define NSTG 2

// Fused attention kernel geometry: global blocks FIRST, then mid blocks.
#define N_ITEMS (BB * NH * SMID)                  // 49104 (divisible by 4)
#define N_MWARPS (N_ITEMS / 4)                    // 12276
#define NBLK_MID ((N_MWARPS + 7) / 8)             // 1535
#define NBLK_GLB (BB * NH * 2)                    // 48

// ---------------------------------------------------------------------------
// Scratch
// ---------------------------------------------------------------------------
__device__ float g_v[MROWS * DD];
__device__ float g_vsum[BB * DD];

__device__ __half g_qp[MROWS * DD];
__device__ __half g_kp[MROWS * DD];
__device__ __half g_qh[MROWS * DD];
__device__ __half g_kh[MROWS * DD];
__device__ __half g_vh[MROWS * DD], g_vl[MROWS * DD];
__device__ __half g_ah[MROWS * DD], g_al[MROWS * DD];
__device__ __half g_wqh[DD * DD];
__device__ __half g_wkh[DD * DD];
__device__ __half g_wvh[DD * DD], g_wvl[DD * DD];
__device__ __half g_woh[DD * DD], g_wol[DD * DD];

// ---------------------------------------------------------------------------
// PTX helpers (portable sm_80+ ISA)
// ---------------------------------------------------------------------------
__device__ __forceinline__ uint32_t smem_u32(const void* p) {
    uint32_t a;
    asm("{ .reg .u64 t; cvta.to.shared.u64 t, %1; cvt.u32.u64 %0, t; }"
        : "=r"(a) : "l"(p));
    return a;
}
__device__ __forceinline__ void cp_async16(uint32_t dst, const void* src) {
    asm volatile("cp.async.cg.shared.global [%0], [%1], 16;"
                 :: "r"(dst), "l"(src) : "memory");
}
__device__ __forceinline__ void cp_commit() {
    asm volatile("cp.async.commit_group;" ::: "memory");
}
template <int N>
__device__ __forceinline__ void cp_wait() {
    asm volatile("cp.async.wait_group %0;" :: "n"(N) : "memory");
}
__device__ __forceinline__ void ldm4(uint32_t* r, uint32_t addr) {
    asm volatile("ldmatrix.sync.aligned.m8n8.x4.shared.b16 {%0,%1,%2,%3}, [%4];"
                 : "=r"(r[0]), "=r"(r[1]), "=r"(r[2]), "=r"(r[3]) : "r"(addr));
}
__device__ __forceinline__ void mma16816(float* c, const uint32_t* a, const uint32_t* b) {
    asm volatile(
        "mma.sync.aligned.m16n8k16.row.col.f32.f16.f16.f32 "
        "{%0,%1,%2,%3}, {%4,%5,%6,%7}, {%8,%9}, {%0,%1,%2,%3};"
        : "+f"(c[0]), "+f"(c[1]), "+f"(c[2]), "+f"(c[3])
        : "r"(a[0]), "r"(a[1]), "r"(a[2]), "r"(a[3]), "r"(b[0]), "r"(b[1]));
}

struct GemmArgs {
    const __half *Ah, *Al, *Bh, *Bl;
    float* C;
    __half* Ch;
    float* vsum;
    int nprod;
};
struct Gemm3 { GemmArgs g[3]; };

// ---------------------------------------------------------------------------
// GEMM (unchanged from round 8 best)
// ---------------------------------------------------------------------------
template <int BNT>
__global__ __launch_bounds__(256, 2) void gemm_mma(Gemm3 ga)
{
    constexpr int WNT = BNT / 4;
    constexpr int NJ = WNT / 8;
    constexpr int TILEB_A = 128 * LDT * 2;
    constexpr int TILEB_B = BNT * LDT * 2;
    constexpr int STAGEB = 2 * TILEB_A + 2 * TILEB_B;
    constexpr int NCHUNK = (2 * 128 + 2 * BNT) * 4;
    constexpr int PER_THR = NCHUNK / 256;

    extern __shared__ char smem[];
    const GemmArgs& A = ga.g[blockIdx.z];
    const int nprod = A.nprod;
    const uint32_t sb = smem_u32(smem);
    const int tid = threadIdx.x;
    const int wid = tid >> 5;
    const int lane = tid & 31;
    const int bm = blockIdx.y * BM;
    const int bn = blockIdx.x * BNT;
    const int wm = (wid >> 2) * 64;
    const int wn = (wid & 3) * WNT;

    float acc[4][NJ][4];
    #pragma unroll
    for (int i = 0; i < 4; i++)
        #pragma unroll
        for (int j = 0; j < NJ; j++)
            #pragma unroll
            for (int e = 0; e < 4; e++) acc[i][j][e] = 0.0f;

    auto issue = [&](int kt) {
        const int st = kt % NSTG;
        #pragma unroll
        for (int q8 = 0; q8 < PER_THR; q8++) {
            int q = tid + q8 * 256;
            if (q < 1024) {
                int t = q >> 9;
                if (t == 1 && nprod < 3) continue;
                int r = (q >> 2) & 127;
                int c = q & 3;
                const __half* src = (t ? A.Al : A.Ah)
                                    + (size_t)(bm + r) * DD + kt * BKK + c * 8;
                uint32_t dst = sb + st * STAGEB + t * TILEB_A + r * (LDT * 2) + c * 16;
                cp_async16(dst, src);
            } else {
                int q2 = q - 1024;
                int t = q2 / (BNT * 4);
                if (t == 1 && nprod < 2) continue;
                int r = (q2 >> 2) % BNT;
                int c = q2 & 3;
                const __half* src = (t ? A.Bl : A.Bh)
                                    + (size_t)(bn + r) * DD + kt * BKK + c * 8;
                uint32_t dst = sb + st * STAGEB + 2 * TILEB_A + t * TILEB_B
                             + r * (LDT * 2) + c * 16;
                cp_async16(dst, src);
            }
        }
        cp_commit();
    };

    const int a_row = lane & 15;
    const int a_col = (lane >> 4) * 8;
    const int b_row = (lane & 7) + ((lane >> 4) << 3);
    const int b_col = ((lane >> 3) & 1) * 8;

    auto compute = [&](int kt) {
        const uint32_t base = sb + (kt % NSTG) * STAGEB;
        #pragma unroll
        for (int ks = 0; ks < 2; ks++) {
            const int k0 = ks * 16;
            uint32_t bh[NJ / 2][4], bl[NJ / 2][4];
            #pragma unroll
            for (int nh = 0; nh < NJ / 2; nh++) {
                uint32_t off = (uint32_t)(wn + nh * 16 + b_row) * (LDT * 2)
                             + (k0 + b_col) * 2;
                ldm4(bh[nh], base + 2 * TILEB_A + off);
                if (nprod >= 2)
                    ldm4(bl[nh], base + 2 * TILEB_A + TILEB_B + off);
            }
            uint32_t af[4][4];
            #pragma unroll
            for (int mt = 0; mt < 4; mt++) {
                uint32_t off = (uint32_t)(wm + mt * 16 + a_row) * (LDT * 2)
                             + (k0 + a_col) * 2;
                ldm4(af[mt], base + off);
            }
            if constexpr (NJ == 2) {
                uint32_t alf[4][4];
                if (nprod >= 3) {
                    #pragma unroll
                    for (int mt = 0; mt < 4; mt++) {
                        uint32_t off = (uint32_t)(wm + mt * 16 + a_row) * (LDT * 2)
                                     + (k0 + a_col) * 2;
                        ldm4(alf[mt], base + TILEB_A + off);
                    }
                }
                #pragma unroll
                for (int mt = 0; mt < 4; mt++)
                    #pragma unroll
                    for (int j = 0; j < NJ; j++) {
                        mma16816(acc[mt][j], af[mt], &bh[j >> 1][(j & 1) * 2]);
                        if (nprod >= 2)
                            mma16816(acc[mt][j], af[mt], &bl[j >> 1][(j & 1) * 2]);
                        if (nprod >= 3)
                            mma16816(acc[mt][j], alf[mt], &bh[j >> 1][(j & 1) * 2]);
                    }
            } else {
                #pragma unroll
                for (int mt = 0; mt < 4; mt++)
                    #pragma unroll
                    for (int j = 0; j < NJ; j++) {
                        mma16816(acc[mt][j], af[mt], &bh[j >> 1][(j & 1) * 2]);
                        if (nprod >= 2)
                            mma16816(acc[mt][j], af[mt], &bl[j >> 1][(j & 1) * 2]);
                    }
                if (nprod >= 3) {
                    #pragma unroll
                    for (int mt = 0; mt < 4; mt++) {
                        uint32_t off = (uint32_t)(wm + mt * 16 + a_row) * (LDT * 2)
                                     + (k0 + a_col) * 2;
                        ldm4(af[mt], base + TILEB_A + off);
                    }
                    #pragma unroll
                    for (int mt = 0; mt < 4; mt++)
                        #pragma unroll
                        for (int j = 0; j < NJ; j++)
                            mma16816(acc[mt][j], af[mt], &bh[j >> 1][(j & 1) * 2]);
                }
            }
        }
    };

    issue(0);
    for (int kt = 0; kt < NCHK; kt++) {
        cp_wait<0>();
        __syncthreads();
        if (kt + 1 < NCHK) issue(kt + 1);
        compute(kt);
    }

    if (A.Ch) {
        #pragma unroll
        for (int mt = 0; mt < 4; mt++) {
            #pragma unroll
            for (int j = 0; j < NJ; j++) {
                int row = bm + wm + mt * 16 + (lane >> 2);
                int col = bn + wn + j * 8 + (lane & 3) * 2;
                *reinterpret_cast<__half2*>(A.Ch + (size_t)row * DD + col)
                    = __floats2half2_rn(acc[mt][j][0], acc[mt][j][1]);
                *reinterpret_cast<__half2*>(A.Ch + (size_t)(row + 8) * DD + col)
                    = __floats2half2_rn(acc[mt][j][2], acc[mt][j][3]);
            }
        }
    } else {
        #pragma unroll
        for (int mt = 0; mt < 4; mt++) {
            #pragma unroll
            for (int j = 0; j < NJ; j++) {
                int row = bm + wm + mt * 16 + (lane >> 2);
                int col = bn + wn + j * 8 + (lane & 3) * 2;
                *reinterpret_cast<float2*>(A.C + (size_t)row * DD + col)
                    = make_float2(acc[mt][j][0], acc[mt][j][1]);
                *reinterpret_cast<float2*>(A.C + (size_t)(row + 8) * DD + col)
                    = make_float2(acc[mt][j][2], acc[mt][j][3]);
            }
        }
    }

    if (A.vsum) {
        int b = bm / SS;
        #pragma unroll
        for (int j = 0; j < NJ; j++) {
            float s0 = 0.0f, s1 = 0.0f;
            #pragma unroll
            for (int mt = 0; mt < 4; mt++) {
                s0 += acc[mt][j][0] + acc[mt][j][2];
                s1 += acc[mt][j][1] + acc[mt][j][3];
            }
            #pragma unroll
            for (int o = 4; o < 32; o <<= 1) {
                s0 += __shfl_xor_sync(0xFFFFFFFFu, s0, o);
                s1 += __shfl_xor_sync(0xFFFFFFFFu, s1, o);
            }
            if (lane < 4) {
                int col = bn + wn + j * 8 + lane * 2;
                atomicAdd(&A.vsum[b * DD + col], s0);
                atomicAdd(&A.vsum[b * DD + col + 1], s1);
            }
        }
    }
}

// ---------------------------------------------------------------------------
// fp32 -> (f16 hi, f16 lo) splits
// ---------------------------------------------------------------------------
__device__ __forceinline__ void split4h(float4 v, ushort4& h, ushort4& l) {
    __half b;
    b = __float2half(v.x); h.x = __half_as_ushort(b);
    l.x = __half_as_ushort(__float2half(v.x - __half2float(b)));
    b = __float2half(v.y); h.y = __half_as_ushort(b);
    l.y = __half_as_ushort(__float2half(v.y - __half2float(b)));
    b = __float2half(v.z); h.z = __half_as_ushort(b);
    l.z = __half_as_ushort(__float2half(v.z - __half2float(b)));
    b = __float2half(v.w); h.w = __half_as_ushort(b);
    l.w = __half_as_ushort(__float2half(v.w - __half2float(b)));
}

struct SplitN {
    const float4* x[4];
    ushort4* hi[4];
    ushort4* lo[4];
    int zero_vsum;
};
__global__ void split_multi(SplitN a, int n4)
{
    int w = blockIdx.y;
    int i = blockIdx.x * blockDim.x + threadIdx.x;
    if (a.zero_vsum && w == 0 && i < BB * DD) g_vsum[i] = 0.0f;
    if (i >= n4) return;
    ushort4 h, l;
    split4h(a.x[w][i], h, l);
    a.hi[w][i] = h;
    if (a.lo[w]) a.lo[w][i] = l;
}

// ---------------------------------------------------------------------------
// Fused attention. Blocks [0,NBLK_GLB): global rows (long, start first).
// Blocks [NBLK_GLB, ...): middle rows, 8 lanes per item, 4 items per warp.
// ---------------------------------------------------------------------------
__device__ __forceinline__ void store_hl(size_t off, float v) {
    __half h = __float2half(v);
    g_ah[off] = h;
    g_al[off] = __float2half(v - __half2float(h));
}

__global__ __launch_bounds__(256, 3) void attn_kernel(const int* __restrict__ idx)
{
    if (blockIdx.x >= NBLK_GLB) {
        // ------------------- middle rows -------------------
        int lane = threadIdx.x & 31;
        int grp = lane >> 3;             // 0..3 (item within warp)
        int d = lane & 7;                // 0..7 (dim octet)
        int w = (blockIdx.x - NBLK_GLB) * 8 + (threadIdx.x >> 5);
        if (w * 4 >= N_ITEMS) return;    // uniform per warp (N_ITEMS % 4 == 0)
        int item = w * 4 + grp;

        int i = item % SMID;
        int h = (item / SMID) % NH;
        int b = item / (SMID * NH);
        int s = i + GG;

        // q octet: 8 halves
        const __half* qrow = g_qp + ((size_t)b * SS + s) * DD + h * DK + d * 8;
        uint4 qv = *reinterpret_cast<const uint4*>(qrow);
        float2 qf0 = __half22float2(*reinterpret_cast<__half2*>(&qv.x));
        float2 qf1 = __half22float2(*reinterpret_cast<__half2*>(&qv.y));
        float2 qf2 = __half22float2(*reinterpret_cast<__half2*>(&qv.z));
        float2 qf3 = __half22float2(*reinterpret_cast<__half2*>(&qv.w));

        int cols[NIDX];
        #pragma unroll
        for (int j = 0; j < NIDX; j++) cols[j] = idx[i * NIDX + j];

        // k octets: 6 independent 16B loads (MLP)
        uint4 kv[NIDX];
        #pragma unroll
        for (int j = 0; j < NIDX; j++)
            kv[j] = *reinterpret_cast<const uint4*>(
                g_kp + ((size_t)b * SS + cols[j]) * DD + h * DK + d * 8);

        float sc[NIDX];
        #pragma unroll
        for (int j = 0; j < NIDX; j++) {
            float2 k0 = __half22float2(*reinterpret_cast<__half2*>(&kv[j].x));
            float2 k1 = __half22float2(*reinterpret_cast<__half2*>(&kv[j].y));
            float2 k2 = __half22float2(*reinterpret_cast<__half2*>(&kv[j].z));
            float2 k3 = __half22float2(*reinterpret_cast<__half2*>(&kv[j].w));
            float p = qf0.x * k0.x + qf0.y * k0.y
                    + qf1.x * k1.x + qf1.y * k1.y
                    + qf2.x * k2.x + qf2.y * k2.y
                    + qf3.x * k3.x + qf3.y * k3.y;
            p += __shfl_xor_sync(0xFFFFFFFFu, p, 1);
            p += __shfl_xor_sync(0xFFFFFFFFu, p, 2);
            p += __shfl_xor_sync(0xFFFFFFFFu, p, 4);
            sc[j] = p;
        }

        float wgt[NIDX];
        float denom = (float)SS;
        #pragma unroll
        for (int j = 0; j < NIDX; j++) {
            bool dup = false;
            #pragma unroll
            for (int jj = 0; jj < NIDX; jj++)
                if (jj < j) dup = dup || (cols[jj] == cols[j]);
            float wv = dup ? 0.0f : (expf(sc[j] * 0.125f) - 1.0f);
            wgt[j] = wv;
            denom += wv;
        }

        const float* vs = g_vsum + b * DD + h * DV + d * 8;
        float4 o0 = *reinterpret_cast<const float4*>(vs);
        float4 o1 = *reinterpret_cast<const float4*>(vs + 4);
        #pragma unroll
        for (int j = 0; j < NIDX; j++) {
            const float* vr = g_v + ((size_t)b * SS + cols[j]) * DD + h * DV + d * 8;
            float4 a = *reinterpret_cast<const float4*>(vr);
            float4 c = *reinterpret_cast<const float4*>(vr + 4);
            o0.x = fmaf(wgt[j], a.x, o0.x); o0.y = fmaf(wgt[j], a.y, o0.y);
            o0.z = fmaf(wgt[j], a.z, o0.z); o0.w = fmaf(wgt[j], a.w, o0.w);
            o1.x = fmaf(wgt[j], c.x, o1.x); o1.y = fmaf(wgt[j], c.y, o1.y);
            o1.z = fmaf(wgt[j], c.z, o1.z); o1.w = fmaf(wgt[j], c.w, o1.w);
        }
        float inv = 1.0f / denom;
        float of[8] = {o0.x * inv, o0.y * inv, o0.z * inv, o0.w * inv,
                       o1.x * inv, o1.y * inv, o1.z * inv, o1.w * inv};

        __half2 hi[4], lo[4];
        #pragma unroll
        for (int e = 0; e < 4; e++) {
            __half h0 = __float2half(of[2 * e]);
            __half h1 = __float2half(of[2 * e + 1]);
            hi[e] = __halves2half2(h0, h1);
            lo[e] = __halves2half2(
                __float2half(of[2 * e] - __half2float(h0)),
                __float2half(of[2 * e + 1] - __half2float(h1)));
        }
        size_t base = ((size_t)b * SS + s) * DD + h * DV + d * 8;
        *reinterpret_cast<uint4*>(g_ah + base) = *reinterpret_cast<uint4*>(hi);
        *reinterpret_cast<uint4*>(g_al + base) = *reinterpret_cast<uint4*>(lo);
    } else {
        // ------------------- global rows -------------------
        int item = blockIdx.x;
        int r = item % 2;
        int h = (item / 2) % NH;
        int b = item / (2 * NH);
        int s = r ? (SS - 1) : 0;
        int tid = threadIdx.x;

        __shared__ float sc[SS];
        __shared__ float qs[DK];
        __shared__ float red[256];

        const __half* qrow = g_qp + ((size_t)b * SS + s) * DD + h * DK;
        if (tid < DK) qs[tid] = __half2float(qrow[tid]);
        __syncthreads();

        for (int t = tid; t < SS; t += 256) {
            const __half* krow = g_kp + ((size_t)b * SS + t) * DD + h * DK;
            float p = 0.0f;
            #pragma unroll
            for (int dd = 0; dd < DK; dd++) p = fmaf(qs[dd], __half2float(krow[dd]), p);
            sc[t] = p * 0.125f;
        }
        __syncthreads();

        float m = -1e30f;
        for (int t = tid; t < SS; t += 256) m = fmaxf(m, sc[t]);
        red[tid] = m; __syncthreads();
        for (int o = 128; o > 0; o >>= 1) {
            if (tid < o) red[tid] = fmaxf(red[tid], red[tid + o]);
            __syncthreads();
        }
        m = red[0];
        __syncthreads();

        float sum = 0.0f;
        for (int t = tid; t < SS; t += 256) {
            float e = expf(sc[t] - m);
            sc[t] = e;
            sum += e;
        }
        red[tid] = sum; __syncthreads();
        for (int o = 128; o > 0; o >>= 1) {
            if (tid < o) red[tid] += red[tid + o];
            __syncthreads();
        }
        float inv = 1.0f / red[0];
        __syncthreads();

        int dv = tid % DV;
        int chunk = tid / DV;
        float acc = 0.0f;
        const float* vb = g_v + (size_t)b * SS * DD + h * DV + dv;
        for (int t = chunk * (SS / 4); t < (chunk + 1) * (SS / 4); t++)
            acc = fmaf(sc[t], vb[(size_t)t * DD], acc);
        red[tid] = acc; __syncthreads();
        if (tid < DV) {
            float o = (red[dv] + red[DV + dv] + red[2 * DV + dv] + red[3 * DV + dv]) * inv;
            store_hl(((size_t)b * SS + s) * DD + h * DV + dv, o);
        }
    }
}

// ---------------------------------------------------------------------------
extern "C" void kernel_launch(void* const* d_in, const int* in_sizes, int n_in,
                              void* d_out, int out_size)
{
    const float* Q  = (const float*)d_in[0];
    const float* K  = (const float*)d_in[1];
    const float* V  = (const float*)d_in[2];
    const float* Wq = (const float*)d_in[3];
    const float* Wk = (const float*)d_in[4];
    const float* Wv = (const float*)d_in[5];
    const float* Wo = (const float*)d_in[6];
    const int*   idx = (const int*)d_in[7];
    float* out = (float*)d_out;

    float *pv, *pvs;
    cudaGetSymbolAddress((void**)&pv, g_v);
    cudaGetSymbolAddress((void**)&pvs, g_vsum);

    __half *qp, *kp, *qh, *kh, *vh, *vl, *ah, *al;
    __half *wqh, *wkh, *wvh, *wvl, *woh, *wol;
    cudaGetSymbolAddress((void**)&qp, g_qp);
    cudaGetSymbolAddress((void**)&kp, g_kp);
    cudaGetSymbolAddress((void**)&qh, g_qh);
    cudaGetSymbolAddress((void**)&kh, g_kh);
    cudaGetSymbolAddress((void**)&vh, g_vh);  cudaGetSymbolAddress((void**)&vl, g_vl);
    cudaGetSymbolAddress((void**)&ah, g_ah);  cudaGetSymbolAddress((void**)&al, g_al);
    cudaGetSymbolAddress((void**)&wqh, g_wqh);
    cudaGetSymbolAddress((void**)&wkh, g_wkh);
    cudaGetSymbolAddress((void**)&wvh, g_wvh); cudaGetSymbolAddress((void**)&wvl, g_wvl);
    cudaGetSymbolAddress((void**)&woh, g_woh); cudaGetSymbolAddress((void**)&wol, g_wol);

    constexpr int SMEM128 = NSTG * (2 * 128 * LDT * 2 + 2 * 128 * LDT * 2);
    constexpr int SMEM64  = NSTG * (2 * 128 * LDT * 2 + 2 * 64 * LDT * 2);
    cudaFuncSetAttribute(gemm_mma<128>, cudaFuncAttributeMaxDynamicSharedMemorySize, SMEM128);
    cudaFuncSetAttribute(gemm_mma<64>,  cudaFuncAttributeMaxDynamicSharedMemorySize, SMEM64);

    const int n4_big = MROWS * DD / 4;
    const int n4_w   = DD * DD / 4;
    const int bl_big = (n4_big + 255) / 256;
    const int bl_w   = (n4_w + 255) / 256;

    SplitN si;
    si.x[0] = (const float4*)Q; si.hi[0] = (ushort4*)qh; si.lo[0] = nullptr;
    si.x[1] = (const float4*)K; si.hi[1] = (ushort4*)kh; si.lo[1] = nullptr;
    si.x[2] = (const float4*)V; si.hi[2] = (ushort4*)vh; si.lo[2] = (ushort4*)vl;
    si.x[3] = si.x[0]; si.hi[3] = si.hi[0]; si.lo[3] = nullptr;
    si.zero_vsum = 0;
    split_multi<<<dim3(bl_big, 3), 256>>>(si, n4_big);

    SplitN sw;
    sw.x[0] = (const float4*)Wq; sw.hi[0] = (ushort4*)wqh; sw.lo[0] = nullptr;
    sw.x[1] = (const float4*)Wk; sw.hi[1] = (ushort4*)wkh; sw.lo[1] = nullptr;
    sw.x[2] = (const float4*)Wv; sw.hi[2] = (ushort4*)wvh; sw.lo[2] = (ushort4*)wvl;
    sw.x[3] = (const float4*)Wo; sw.hi[3] = (ushort4*)woh; sw.lo[3] = (ushort4*)wol;
    sw.zero_vsum = 1;
    split_multi<<<dim3(bl_w, 4), 256>>>(sw, n4_w);

    Gemm3 g3;
    g3.g[0] = {qh, nullptr, wqh, nullptr, nullptr, qp, nullptr, 1};
    g3.g[1] = {kh, nullptr, wkh, nullptr, nullptr, kp, nullptr, 1};
    g3.g[2] = {vh, vl,      wvh, wvl,     pv,      nullptr, pvs, 3};
    gemm_mma<128><<<dim3(DD / 128, MROWS / BM, 3), 256, SMEM128>>>(g3);

    attn_kernel<<<NBLK_GLB + NBLK_MID, 256>>>(idx);

    Gemm3 go;
    go.g[0] = {ah, al, woh, wol, out, nullptr, nullptr, 3};
    go.g[1] = go.g[0];
    go.g[2] = go.g[0];
    gemm_mma<64><<<dim3(DD / 64, MROWS / BM, 1), 256, SMEM64>>>(go);
}

// round 11
// speedup vs baseline: 1.1168x; 1.0532x over previous
#include <cuda_runtime.h>
#include <cuda_fp16.h>
#include <cstdint>
#include <math.h>

// Problem constants
#define BB 2
#define SS 2048
#define DD 768
#define NH 12
#define DK 64
#define DV 64
#define GG 1
#define NIDX 6
#define SMID (SS - 2*GG)
#define MROWS (BB * SS)

// GEMM tiling
#define BM 128
#define BKK 32
#define NCHK (DD / BKK)
#define LDT 40
#define NSTG 2

// Fused attention kernel geometry: global blocks FIRST, then mid blocks.
#define N_ITEMS (BB * NH * SMID)                  // 49104 (divisible by 4)
#define N_MWARPS (N_ITEMS / 4)                    // 12276
#define NBLK_MID ((N_MWARPS + 7) / 8)             // 1535
#define NBLK_GLB (BB * NH * 2)                    // 48

// ---------------------------------------------------------------------------
// Scratch
// ---------------------------------------------------------------------------
__device__ float g_v[MROWS * DD];
__device__ float g_vsum[BB * DD];

__device__ __half g_qp[MROWS * DD];
__device__ __half g_kp[MROWS * DD];
__device__ __half g_qh[MROWS * DD];
__device__ __half g_kh[MROWS * DD];
__device__ __half g_vh[MROWS * DD];
__device__ __half g_ah[MROWS * DD], g_al[MROWS * DD];
__device__ __half g_wqh[DD * DD];
__device__ __half g_wkh[DD * DD];
__device__ __half g_wvh[DD * DD], g_wvl[DD * DD];
__device__ __half g_woh[DD * DD], g_wol[DD * DD];

// ---------------------------------------------------------------------------
// PTX helpers (portable sm_80+ ISA)
// ---------------------------------------------------------------------------
__device__ __forceinline__ uint32_t smem_u32(const void* p) {
    uint32_t a;
    asm("{ .reg .u64 t; cvta.to.shared.u64 t, %1; cvt.u32.u64 %0, t; }"
        : "=r"(a) : "l"(p));
    return a;
}
__device__ __forceinline__ void cp_async16(uint32_t dst, const void* src) {
    asm volatile("cp.async.cg.shared.global [%0], [%1], 16;"
                 :: "r"(dst), "l"(src) : "memory");
}
__device__ __forceinline__ void cp_commit() {
    asm volatile("cp.async.commit_group;" ::: "memory");
}
template <int N>
__device__ __forceinline__ void cp_wait() {
    asm volatile("cp.async.wait_group %0;" :: "n"(N) : "memory");
}
__device__ __forceinline__ void ldm4(uint32_t* r, uint32_t addr) {
    asm volatile("ldmatrix.sync.aligned.m8n8.x4.shared.b16 {%0,%1,%2,%3}, [%4];"
                 : "=r"(r[0]), "=r"(r[1]), "=r"(r[2]), "=r"(r[3]) : "r"(addr));
}
__device__ __forceinline__ void mma16816(float* c, const uint32_t* a, const uint32_t* b) {
    asm volatile(
        "mma.sync.aligned.m16n8k16.row.col.f32.f16.f16.f32 "
        "{%0,%1,%2,%3}, {%4,%5,%6,%7}, {%8,%9}, {%0,%1,%2,%3};"
        : "+f"(c[0]), "+f"(c[1]), "+f"(c[2]), "+f"(c[3])
        : "r"(a[0]), "r"(a[1]), "r"(a[2]), "r"(a[3]), "r"(b[0]), "r"(b[1]));
}

struct GemmArgs {
    const __half *Ah, *Al, *Bh, *Bl;
    float* C;
    __half* Ch;
    float* vsum;
    int nprod;        // 1: Ah*Bh ; 2: + Ah*Bl ; 3: + Al*Bh
};
struct Gemm3 { GemmArgs g[3]; };

// ---------------------------------------------------------------------------
// GEMM
// ---------------------------------------------------------------------------
template <int BNT>
__global__ __launch_bounds__(256, 2) void gemm_mma(Gemm3 ga)
{
    constexpr int WNT = BNT / 4;
    constexpr int NJ = WNT / 8;
    constexpr int TILEB_A = 128 * LDT * 2;
    constexpr int TILEB_B = BNT * LDT * 2;
    constexpr int STAGEB = 2 * TILEB_A + 2 * TILEB_B;
    constexpr int NCHUNK = (2 * 128 + 2 * BNT) * 4;
    constexpr int PER_THR = NCHUNK / 256;

    extern __shared__ char smem[];
    const GemmArgs& A = ga.g[blockIdx.z];
    const int nprod = A.nprod;
    const uint32_t sb = smem_u32(smem);
    const int tid = threadIdx.x;
    const int wid = tid >> 5;
    const int lane = tid & 31;
    const int bm = blockIdx.y * BM;
    const int bn = blockIdx.x * BNT;
    const int wm = (wid >> 2) * 64;
    const int wn = (wid & 3) * WNT;

    float acc[4][NJ][4];
    #pragma unroll
    for (int i = 0; i < 4; i++)
        #pragma unroll
        for (int j = 0; j < NJ; j++)
            #pragma unroll
            for (int e = 0; e < 4; e++) acc[i][j][e] = 0.0f;

    auto issue = [&](int kt) {
        const int st = kt % NSTG;
        #pragma unroll
        for (int q8 = 0; q8 < PER_THR; q8++) {
            int q = tid + q8 * 256;
            if (q < 1024) {
                int t = q >> 9;
                if (t == 1 && nprod < 3) continue;
                int r = (q >> 2) & 127;
                int c = q & 3;
                const __half* src = (t ? A.Al : A.Ah)
                                    + (size_t)(bm + r) * DD + kt * BKK + c * 8;
                uint32_t dst = sb + st * STAGEB + t * TILEB_A + r * (LDT * 2) + c * 16;
                cp_async16(dst, src);
            } else {
                int q2 = q - 1024;
                int t = q2 / (BNT * 4);
                if (t == 1 && nprod < 2) continue;
                int r = (q2 >> 2) % BNT;
                int c = q2 & 3;
                const __half* src = (t ? A.Bl : A.Bh)
                                    + (size_t)(bn + r) * DD + kt * BKK + c * 8;
                uint32_t dst = sb + st * STAGEB + 2 * TILEB_A + t * TILEB_B
                             + r * (LDT * 2) + c * 16;
                cp_async16(dst, src);
            }
        }
        cp_commit();
    };

    const int a_row = lane & 15;
    const int a_col = (lane >> 4) * 8;
    const int b_row = (lane & 7) + ((lane >> 4) << 3);
    const int b_col = ((lane >> 3) & 1) * 8;

    auto compute = [&](int kt) {
        const uint32_t base = sb + (kt % NSTG) * STAGEB;
        #pragma unroll
        for (int ks = 0; ks < 2; ks++) {
            const int k0 = ks * 16;
            uint32_t bh[NJ / 2][4], bl[NJ / 2][4];
            #pragma unroll
            for (int nh = 0; nh < NJ / 2; nh++) {
                uint32_t off = (uint32_t)(wn + nh * 16 + b_row) * (LDT * 2)
                             + (k0 + b_col) * 2;
                ldm4(bh[nh], base + 2 * TILEB_A + off);
                if (nprod >= 2)
                    ldm4(bl[nh], base + 2 * TILEB_A + TILEB_B + off);
            }
            uint32_t af[4][4];
            #pragma unroll
            for (int mt = 0; mt < 4; mt++) {
                uint32_t off = (uint32_t)(wm + mt * 16 + a_row) * (LDT * 2)
                             + (k0 + a_col) * 2;
                ldm4(af[mt], base + off);
            }
            if constexpr (NJ == 2) {
                uint32_t alf[4][4];
                if (nprod >= 3) {
                    #pragma unroll
                    for (int mt = 0; mt < 4; mt++) {
                        uint32_t off = (uint32_t)(wm + mt * 16 + a_row) * (LDT * 2)
                                     + (k0 + a_col) * 2;
                        ldm4(alf[mt], base + TILEB_A + off);
                    }
                }
                #pragma unroll
                for (int mt = 0; mt < 4; mt++)
                    #pragma unroll
                    for (int j = 0; j < NJ; j++) {
                        mma16816(acc[mt][j], af[mt], &bh[j >> 1][(j & 1) * 2]);
                        if (nprod >= 2)
                            mma16816(acc[mt][j], af[mt], &bl[j >> 1][(j & 1) * 2]);
                        if (nprod >= 3)
                            mma16816(acc[mt][j], alf[mt], &bh[j >> 1][(j & 1) * 2]);
                    }
            } else {
                #pragma unroll
                for (int mt = 0; mt < 4; mt++)
                    #pragma unroll
                    for (int j = 0; j < NJ; j++) {
                        mma16816(acc[mt][j], af[mt], &bh[j >> 1][(j & 1) * 2]);
                        if (nprod >= 2)
                            mma16816(acc[mt][j], af[mt], &bl[j >> 1][(j & 1) * 2]);
                    }
                if (nprod >= 3) {
                    #pragma unroll
                    for (int mt = 0; mt < 4; mt++) {
                        uint32_t off = (uint32_t)(wm + mt * 16 + a_row) * (LDT * 2)
                                     + (k0 + a_col) * 2;
                        ldm4(af[mt], base + TILEB_A + off);
                    }
                    #pragma unroll
                    for (int mt = 0; mt < 4; mt++)
                        #pragma unroll
                        for (int j = 0; j < NJ; j++)
                            mma16816(acc[mt][j], af[mt], &bh[j >> 1][(j & 1) * 2]);
                }
            }
        }
    };

    issue(0);
    for (int kt = 0; kt < NCHK; kt++) {
        cp_wait<0>();
        __syncthreads();
        if (kt + 1 < NCHK) issue(kt + 1);
        compute(kt);
    }

    if (A.Ch) {
        #pragma unroll
        for (int mt = 0; mt < 4; mt++) {
            #pragma unroll
            for (int j = 0; j < NJ; j++) {
                int row = bm + wm + mt * 16 + (lane >> 2);
                int col = bn + wn + j * 8 + (lane & 3) * 2;
                *reinterpret_cast<__half2*>(A.Ch + (size_t)row * DD + col)
                    = __floats2half2_rn(acc[mt][j][0], acc[mt][j][1]);
                *reinterpret_cast<__half2*>(A.Ch + (size_t)(row + 8) * DD + col)
                    = __floats2half2_rn(acc[mt][j][2], acc[mt][j][3]);
            }
        }
    } else {
        #pragma unroll
        for (int mt = 0; mt < 4; mt++) {
            #pragma unroll
            for (int j = 0; j < NJ; j++) {
                int row = bm + wm + mt * 16 + (lane >> 2);
                int col = bn + wn + j * 8 + (lane & 3) * 2;
                *reinterpret_cast<float2*>(A.C + (size_t)row * DD + col)
                    = make_float2(acc[mt][j][0], acc[mt][j][1]);
                *reinterpret_cast<float2*>(A.C + (size_t)(row + 8) * DD + col)
                    = make_float2(acc[mt][j][2], acc[mt][j][3]);
            }
        }
    }

    if (A.vsum) {
        int b = bm / SS;
        #pragma unroll
        for (int j = 0; j < NJ; j++) {
            float s0 = 0.0f, s1 = 0.0f;
            #pragma unroll
            for (int mt = 0; mt < 4; mt++) {
                s0 += acc[mt][j][0] + acc[mt][j][2];
                s1 += acc[mt][j][1] + acc[mt][j][3];
            }
            #pragma unroll
            for (int o = 4; o < 32; o <<= 1) {
                s0 += __shfl_xor_sync(0xFFFFFFFFu, s0, o);
                s1 += __shfl_xor_sync(0xFFFFFFFFu, s1, o);
            }
            if (lane < 4) {
                int col = bn + wn + j * 8 + lane * 2;
                atomicAdd(&A.vsum[b * DD + col], s0);
                atomicAdd(&A.vsum[b * DD + col + 1], s1);
            }
        }
    }
}

// ---------------------------------------------------------------------------
// fp32 -> (f16 hi, f16 lo) splits
// ---------------------------------------------------------------------------
__device__ __forceinline__ void split4h(float4 v, ushort4& h, ushort4& l) {
    __half b;
    b = __float2half(v.x); h.x = __half_as_ushort(b);
    l.x = __half_as_ushort(__float2half(v.x - __half2float(b)));
    b = __float2half(v.y); h.y = __half_as_ushort(b);
    l.y = __half_as_ushort(__float2half(v.y - __half2float(b)));
    b = __float2half(v.z); h.z = __half_as_ushort(b);
    l.z = __half_as_ushort(__float2half(v.z - __half2float(b)));
    b = __float2half(v.w); h.w = __half_as_ushort(b);
    l.w = __half_as_ushort(__float2half(v.w - __half2float(b)));
}

struct SplitN {
    const float4* x[4];
    ushort4* hi[4];
    ushort4* lo[4];
    int zero_vsum;
};
__global__ void split_multi(SplitN a, int n4)
{
    int w = blockIdx.y;
    int i = blockIdx.x * blockDim.x + threadIdx.x;
    if (a.zero_vsum && w == 0 && i < BB * DD) g_vsum[i] = 0.0f;
    if (i >= n4) return;
    ushort4 h, l;
    split4h(a.x[w][i], h, l);
    a.hi[w][i] = h;
    if (a.lo[w]) a.lo[w][i] = l;
}

// ---------------------------------------------------------------------------
// Fused attention. Blocks [0,NBLK_GLB): global rows (long, start first).
// Blocks [NBLK_GLB, ...): middle rows, 8 lanes per item, 4 items per warp.
// ---------------------------------------------------------------------------
__device__ __forceinline__ void store_hl(size_t off, float v) {
    __half h = __float2half(v);
    g_ah[off] = h;
    g_al[off] = __float2half(v - __half2float(h));
}

__global__ __launch_bounds__(256, 4) void attn_kernel(const int* __restrict__ idx)
{
    if (blockIdx.x >= NBLK_GLB) {
        // ------------------- middle rows -------------------
        int lane = threadIdx.x & 31;
        int grp = lane >> 3;
        int d = lane & 7;
        int w = (blockIdx.x - NBLK_GLB) * 8 + (threadIdx.x >> 5);
        if (w * 4 >= N_ITEMS) return;
        int item = w * 4 + grp;

        int i = item % SMID;
        int h = (item / SMID) % NH;
        int b = item / (SMID * NH);
        int s = i + GG;

        const __half* qrow = g_qp + ((size_t)b * SS + s) * DD + h * DK + d * 8;
        uint4 qv = *reinterpret_cast<const uint4*>(qrow);
        float2 qf0 = __half22float2(*reinterpret_cast<__half2*>(&qv.x));
        float2 qf1 = __half22float2(*reinterpret_cast<__half2*>(&qv.y));
        float2 qf2 = __half22float2(*reinterpret_cast<__half2*>(&qv.z));
        float2 qf3 = __half22float2(*reinterpret_cast<__half2*>(&qv.w));

        int cols[NIDX];
        #pragma unroll
        for (int j = 0; j < NIDX; j++) cols[j] = idx[i * NIDX + j];

        uint4 kv[NIDX];
        #pragma unroll
        for (int j = 0; j < NIDX; j++)
            kv[j] = *reinterpret_cast<const uint4*>(
                g_kp + ((size_t)b * SS + cols[j]) * DD + h * DK + d * 8);

        float sc[NIDX];
        #pragma unroll
        for (int j = 0; j < NIDX; j++) {
            float2 k0 = __half22float2(*reinterpret_cast<__half2*>(&kv[j].x));
            float2 k1 = __half22float2(*reinterpret_cast<__half2*>(&kv[j].y));
            float2 k2 = __half22float2(*reinterpret_cast<__half2*>(&kv[j].z));
            float2 k3 = __half22float2(*reinterpret_cast<__half2*>(&kv[j].w));
            float p = qf0.x * k0.x + qf0.y * k0.y
                    + qf1.x * k1.x + qf1.y * k1.y
                    + qf2.x * k2.x + qf2.y * k2.y
                    + qf3.x * k3.x + qf3.y * k3.y;
            p += __shfl_xor_sync(0xFFFFFFFFu, p, 1);
            p += __shfl_xor_sync(0xFFFFFFFFu, p, 2);
            p += __shfl_xor_sync(0xFFFFFFFFu, p, 4);
            sc[j] = p;
        }

        float wgt[NIDX];
        float denom = (float)SS;
        #pragma unroll
        for (int j = 0; j < NIDX; j++) {
            bool dup = false;
            #pragma unroll
            for (int jj = 0; jj < NIDX; jj++)
                if (jj < j) dup = dup || (cols[jj] == cols[j]);
            float wv = dup ? 0.0f : (expf(sc[j] * 0.125f) - 1.0f);
            wgt[j] = wv;
            denom += wv;
        }

        const float* vs = g_vsum + b * DD + h * DV + d * 8;
        float4 o0 = *reinterpret_cast<const float4*>(vs);
        float4 o1 = *reinterpret_cast<const float4*>(vs + 4);
        #pragma unroll
        for (int j = 0; j < NIDX; j++) {
            const float* vr = g_v + ((size_t)b * SS + cols[j]) * DD + h * DV + d * 8;
            float4 a = *reinterpret_cast<const float4*>(vr);
            float4 c = *reinterpret_cast<const float4*>(vr + 4);
            o0.x = fmaf(wgt[j], a.x, o0.x); o0.y = fmaf(wgt[j], a.y, o0.y);
            o0.z = fmaf(wgt[j], a.z, o0.z); o0.w = fmaf(wgt[j], a.w, o0.w);
            o1.x = fmaf(wgt[j], c.x, o1.x); o1.y = fmaf(wgt[j], c.y, o1.y);
            o1.z = fmaf(wgt[j], c.z, o1.z); o1.w = fmaf(wgt[j], c.w, o1.w);
        }
        float inv = 1.0f / denom;
        float of[8] = {o0.x * inv, o0.y * inv, o0.z * inv, o0.w * inv,
                       o1.x * inv, o1.y * inv, o1.z * inv, o1.w * inv};

        __half2 hi[4], lo[4];
        #pragma unroll
        for (int e = 0; e < 4; e++) {
            __half h0 = __float2half(of[2 * e]);
            __half h1 = __float2half(of[2 * e + 1]);
            hi[e] = __halves2half2(h0, h1);
            lo[e] = __halves2half2(
                __float2half(of[2 * e] - __half2float(h0)),
                __float2half(of[2 * e + 1] - __half2float(h1)));
        }
        size_t base = ((size_t)b * SS + s) * DD + h * DV + d * 8;
        *reinterpret_cast<uint4*>(g_ah + base) = *reinterpret_cast<uint4*>(hi);
        *reinterpret_cast<uint4*>(g_al + base) = *reinterpret_cast<uint4*>(lo);
    } else {
        // ------------------- global rows -------------------
        int item = blockIdx.x;
        int r = item % 2;
        int h = (item / 2) % NH;
        int b = item / (2 * NH);
        int s = r ? (SS - 1) : 0;
        int tid = threadIdx.x;

        __shared__ float sc[SS];
        __shared__ float qs[DK];
        __shared__ float red[256];

        const __half* qrow = g_qp + ((size_t)b * SS + s) * DD + h * DK;
        if (tid < DK) qs[tid] = __half2float(qrow[tid]);
        __syncthreads();

        for (int t = tid; t < SS; t += 256) {
            const __half* krow = g_kp + ((size_t)b * SS + t) * DD + h * DK;
            float p = 0.0f;
            #pragma unroll
            for (int dd = 0; dd < DK; dd++) p = fmaf(qs[dd], __half2float(krow[dd]), p);
            sc[t] = p * 0.125f;
        }
        __syncthreads();

        float m = -1e30f;
        for (int t = tid; t < SS; t += 256) m = fmaxf(m, sc[t]);
        red[tid] = m; __syncthreads();
        for (int o = 128; o > 0; o >>= 1) {
            if (tid < o) red[tid] = fmaxf(red[tid], red[tid + o]);
            __syncthreads();
        }
        m = red[0];
        __syncthreads();

        float sum = 0.0f;
        for (int t = tid; t < SS; t += 256) {
            float e = expf(sc[t] - m);
            sc[t] = e;
            sum += e;
        }
        red[tid] = sum; __syncthreads();
        for (int o = 128; o > 0; o >>= 1) {
            if (tid < o) red[tid] += red[tid + o];
            __syncthreads();
        }
        float inv = 1.0f / red[0];
        __syncthreads();

        int dv = tid % DV;
        int chunk = tid / DV;
        float acc = 0.0f;
        const float* vb = g_v + (size_t)b * SS * DD + h * DV + dv;
        for (int t = chunk * (SS / 4); t < (chunk + 1) * (SS / 4); t++)
            acc = fmaf(sc[t], vb[(size_t)t * DD], acc);
        red[tid] = acc; __syncthreads();
        if (tid < DV) {
            float o = (red[dv] + red[DV + dv] + red[2 * DV + dv] + red[3 * DV + dv]) * inv;
            store_hl(((size_t)b * SS + s) * DD + h * DV + dv, o);
        }
    }
}

// ---------------------------------------------------------------------------
extern "C" void kernel_launch(void* const* d_in, const int* in_sizes, int n_in,
                              void* d_out, int out_size)
{
    const float* Q  = (const float*)d_in[0];
    const float* K  = (const float*)d_in[1];
    const float* V  = (const float*)d_in[2];
    const float* Wq = (const float*)d_in[3];
    const float* Wk = (const float*)d_in[4];
    const float* Wv = (const float*)d_in[5];
    const float* Wo = (const float*)d_in[6];
    const int*   idx = (const int*)d_in[7];
    float* out = (float*)d_out;

    float *pv, *pvs;
    cudaGetSymbolAddress((void**)&pv, g_v);
    cudaGetSymbolAddress((void**)&pvs, g_vsum);

    __half *qp, *kp, *qh, *kh, *vh, *ah, *al;
    __half *wqh, *wkh, *wvh, *wvl, *woh, *wol;
    cudaGetSymbolAddress((void**)&qp, g_qp);
    cudaGetSymbolAddress((void**)&kp, g_kp);
    cudaGetSymbolAddress((void**)&qh, g_qh);
    cudaGetSymbolAddress((void**)&kh, g_kh);
    cudaGetSymbolAddress((void**)&vh, g_vh);
    cudaGetSymbolAddress((void**)&ah, g_ah);  cudaGetSymbolAddress((void**)&al, g_al);
    cudaGetSymbolAddress((void**)&wqh, g_wqh);
    cudaGetSymbolAddress((void**)&wkh, g_wkh);
    cudaGetSymbolAddress((void**)&wvh, g_wvh); cudaGetSymbolAddress((void**)&wvl, g_wvl);
    cudaGetSymbolAddress((void**)&woh, g_woh); cudaGetSymbolAddress((void**)&wol, g_wol);

    constexpr int SMEM128 = NSTG * (2 * 128 * LDT * 2 + 2 * 128 * LDT * 2);
    constexpr int SMEM64  = NSTG * (2 * 128 * LDT * 2 + 2 * 64 * LDT * 2);
    cudaFuncSetAttribute(gemm_mma<128>, cudaFuncAttributeMaxDynamicSharedMemorySize, SMEM128);
    cudaFuncSetAttribute(gemm_mma<64>,  cudaFuncAttributeMaxDynamicSharedMemorySize, SMEM64);

    const int n4_big = MROWS * DD / 4;
    const int n4_w   = DD * DD / 4;
    const int bl_big = (n4_big + 255) / 256;
    const int bl_w   = (n4_w + 255) / 256;

    SplitN si;
    si.x[0] = (const float4*)Q; si.hi[0] = (ushort4*)qh; si.lo[0] = nullptr;
    si.x[1] = (const float4*)K; si.hi[1] = (ushort4*)kh; si.lo[1] = nullptr;
    si.x[2] = (const float4*)V; si.hi[2] = (ushort4*)vh; si.lo[2] = nullptr;
    si.x[3] = si.x[0]; si.hi[3] = si.hi[0]; si.lo[3] = nullptr;
    si.zero_vsum = 0;
    split_multi<<<dim3(bl_big, 3), 256>>>(si, n4_big);

    SplitN sw;
    sw.x[0] = (const float4*)Wq; sw.hi[0] = (ushort4*)wqh; sw.lo[0] = nullptr;
    sw.x[1] = (const float4*)Wk; sw.hi[1] = (ushort4*)wkh; sw.lo[1] = nullptr;
    sw.x[2] = (const float4*)Wv; sw.hi[2] = (ushort4*)wvh; sw.lo[2] = (ushort4*)wvl;
    sw.x[3] = (const float4*)Wo; sw.hi[3] = (ushort4*)woh; sw.lo[3] = (ushort4*)wol;
    sw.zero_vsum = 1;
    split_multi<<<dim3(bl_w, 4), 256>>>(sw, n4_w);

    // V slice first (heaviest: 2 products + vsum) so heavy CTAs don't trail.
    Gemm3 g3;
    g3.g[0] = {vh, nullptr, wvh, wvl, pv, nullptr, pvs, 2};
    g3.g[1] = {qh, nullptr, wqh, nullptr, nullptr, qp, nullptr, 1};
    g3.g[2] = {kh, nullptr, wkh, nullptr, nullptr, kp, nullptr, 1};
    gemm_mma<128><<<dim3(DD / 128, MROWS / BM, 3), 256, SMEM128>>>(g3);

    attn_kernel<<<NBLK_GLB + NBLK_MID, 256>>>(idx);

    Gemm3 go;
    go.g[0] = {ah, al, woh, wol, out, nullptr, nullptr, 3};
    go.g[1] = go.g[0];
    go.g[2] = go.g[0];
    gemm_mma<64><<<dim3(DD / 64, MROWS / BM, 1), 256, SMEM64>>>(go);
}

// round 12
// speedup vs baseline: 1.1312x; 1.0129x over previous
#include <cuda_runtime.h>
#include <cuda_fp16.h>
#include <cstdint>
#include <math.h>

// Problem constants
#define BB 2
#define SS 2048
#define DD 768
#define NH 12
#define DK 64
#define DV 64
#define GG 1
#define NIDX 6
#define SMID (SS - 2*GG)
#define MROWS (BB * SS)

// GEMM tiling
#define BM 128
#define BKK 32
#define NCHK (DD / BKK)
#define LDT 40
#define NSTG 2

// Fused attention kernel geometry: global blocks FIRST, then mid blocks.
#define N_ITEMS (BB * NH * SMID)                  // 49104 (divisible by 4)
#define N_MWARPS (N_ITEMS / 4)                    // 12276
#define NBLK_MID ((N_MWARPS + 7) / 8)             // 1535
#define NBLK_GLB (BB * NH * 2)                    // 48

// ---------------------------------------------------------------------------
// Scratch
// ---------------------------------------------------------------------------
__device__ float g_vsum[BB * DD];

__device__ __half g_qp[MROWS * DD];          // projected q (f16)
__device__ __half g_kp[MROWS * DD];          // projected k (f16)
__device__ __half g_vp[MROWS * DD];          // projected v (f16)
__device__ __half g_qh[MROWS * DD];
__device__ __half g_kh[MROWS * DD];
__device__ __half g_vh[MROWS * DD];
__device__ __half g_ah[MROWS * DD], g_al[MROWS * DD];
__device__ __half g_wqh[DD * DD];
__device__ __half g_wkh[DD * DD];
__device__ __half g_wvh[DD * DD], g_wvl[DD * DD];
__device__ __half g_woh[DD * DD], g_wol[DD * DD];

// ---------------------------------------------------------------------------
// PTX helpers (portable sm_80+ ISA)
// ---------------------------------------------------------------------------
__device__ __forceinline__ uint32_t smem_u32(const void* p) {
    uint32_t a;
    asm("{ .reg .u64 t; cvta.to.shared.u64 t, %1; cvt.u32.u64 %0, t; }"
        : "=r"(a) : "l"(p));
    return a;
}
__device__ __forceinline__ void cp_async16(uint32_t dst, const void* src) {
    asm volatile("cp.async.cg.shared.global [%0], [%1], 16;"
                 :: "r"(dst), "l"(src) : "memory");
}
__device__ __forceinline__ void cp_commit() {
    asm volatile("cp.async.commit_group;" ::: "memory");
}
template <int N>
__device__ __forceinline__ void cp_wait() {
    asm volatile("cp.async.wait_group %0;" :: "n"(N) : "memory");
}
__device__ __forceinline__ void ldm4(uint32_t* r, uint32_t addr) {
    asm volatile("ldmatrix.sync.aligned.m8n8.x4.shared.b16 {%0,%1,%2,%3}, [%4];"
                 : "=r"(r[0]), "=r"(r[1]), "=r"(r[2]), "=r"(r[3]) : "r"(addr));
}
__device__ __forceinline__ void mma16816(float* c, const uint32_t* a, const uint32_t* b) {
    asm volatile(
        "mma.sync.aligned.m16n8k16.row.col.f32.f16.f16.f32 "
        "{%0,%1,%2,%3}, {%4,%5,%6,%7}, {%8,%9}, {%0,%1,%2,%3};"
        : "+f"(c[0]), "+f"(c[1]), "+f"(c[2]), "+f"(c[3])
        : "r"(a[0]), "r"(a[1]), "r"(a[2]), "r"(a[3]), "r"(b[0]), "r"(b[1]));
}

struct GemmArgs {
    const __half *Ah, *Al, *Bh, *Bl;
    float* C;         // fp32 output (when Ch == nullptr)
    __half* Ch;       // f16 output
    float* vsum;      // non-null: accumulate per-batch column sums
    int nprod;        // 1: Ah*Bh ; 2: + Ah*Bl ; 3: + Al*Bh
};
struct Gemm3 { GemmArgs g[3]; };

// ---------------------------------------------------------------------------
// GEMM
// ---------------------------------------------------------------------------
template <int BNT>
__global__ __launch_bounds__(256, 2) void gemm_mma(Gemm3 ga)
{
    constexpr int WNT = BNT / 4;
    constexpr int NJ = WNT / 8;
    constexpr int TILEB_A = 128 * LDT * 2;
    constexpr int TILEB_B = BNT * LDT * 2;
    constexpr int STAGEB = 2 * TILEB_A + 2 * TILEB_B;
    constexpr int NCHUNK = (2 * 128 + 2 * BNT) * 4;
    constexpr int PER_THR = NCHUNK / 256;

    extern __shared__ char smem[];
    const GemmArgs& A = ga.g[blockIdx.z];
    const int nprod = A.nprod;
    const uint32_t sb = smem_u32(smem);
    const int tid = threadIdx.x;
    const int wid = tid >> 5;
    const int lane = tid & 31;
    const int bm = blockIdx.y * BM;
    const int bn = blockIdx.x * BNT;
    const int wm = (wid >> 2) * 64;
    const int wn = (wid & 3) * WNT;

    float acc[4][NJ][4];
    #pragma unroll
    for (int i = 0; i < 4; i++)
        #pragma unroll
        for (int j = 0; j < NJ; j++)
            #pragma unroll
            for (int e = 0; e < 4; e++) acc[i][j][e] = 0.0f;

    auto issue = [&](int kt) {
        const int st = kt % NSTG;
        #pragma unroll
        for (int q8 = 0; q8 < PER_THR; q8++) {
            int q = tid + q8 * 256;
            if (q < 1024) {
                int t = q >> 9;
                if (t == 1 && nprod < 3) continue;
                int r = (q >> 2) & 127;
                int c = q & 3;
                const __half* src = (t ? A.Al : A.Ah)
                                    + (size_t)(bm + r) * DD + kt * BKK + c * 8;
                uint32_t dst = sb + st * STAGEB + t * TILEB_A + r * (LDT * 2) + c * 16;
                cp_async16(dst, src);
            } else {
                int q2 = q - 1024;
                int t = q2 / (BNT * 4);
                if (t == 1 && nprod < 2) continue;
                int r = (q2 >> 2) % BNT;
                int c = q2 & 3;
                const __half* src = (t ? A.Bl : A.Bh)
                                    + (size_t)(bn + r) * DD + kt * BKK + c * 8;
                uint32_t dst = sb + st * STAGEB + 2 * TILEB_A + t * TILEB_B
                             + r * (LDT * 2) + c * 16;
                cp_async16(dst, src);
            }
        }
        cp_commit();
    };

    const int a_row = lane & 15;
    const int a_col = (lane >> 4) * 8;
    const int b_row = (lane & 7) + ((lane >> 4) << 3);
    const int b_col = ((lane >> 3) & 1) * 8;

    auto compute = [&](int kt) {
        const uint32_t base = sb + (kt % NSTG) * STAGEB;
        #pragma unroll
        for (int ks = 0; ks < 2; ks++) {
            const int k0 = ks * 16;
            uint32_t bh[NJ / 2][4], bl[NJ / 2][4];
            #pragma unroll
            for (int nh = 0; nh < NJ / 2; nh++) {
                uint32_t off = (uint32_t)(wn + nh * 16 + b_row) * (LDT * 2)
                             + (k0 + b_col) * 2;
                ldm4(bh[nh], base + 2 * TILEB_A + off);
                if (nprod >= 2)
                    ldm4(bl[nh], base + 2 * TILEB_A + TILEB_B + off);
            }
            uint32_t af[4][4];
            #pragma unroll
            for (int mt = 0; mt < 4; mt++) {
                uint32_t off = (uint32_t)(wm + mt * 16 + a_row) * (LDT * 2)
                             + (k0 + a_col) * 2;
                ldm4(af[mt], base + off);
            }
            if constexpr (NJ == 2) {
                uint32_t alf[4][4];
                if (nprod >= 3) {
                    #pragma unroll
                    for (int mt = 0; mt < 4; mt++) {
                        uint32_t off = (uint32_t)(wm + mt * 16 + a_row) * (LDT * 2)
                                     + (k0 + a_col) * 2;
                        ldm4(alf[mt], base + TILEB_A + off);
                    }
                }
                #pragma unroll
                for (int mt = 0; mt < 4; mt++)
                    #pragma unroll
                    for (int j = 0; j < NJ; j++) {
                        mma16816(acc[mt][j], af[mt], &bh[j >> 1][(j & 1) * 2]);
                        if (nprod >= 2)
                            mma16816(acc[mt][j], af[mt], &bl[j >> 1][(j & 1) * 2]);
                        if (nprod >= 3)
                            mma16816(acc[mt][j], alf[mt], &bh[j >> 1][(j & 1) * 2]);
                    }
            } else {
                #pragma unroll
                for (int mt = 0; mt < 4; mt++)
                    #pragma unroll
                    for (int j = 0; j < NJ; j++) {
                        mma16816(acc[mt][j], af[mt], &bh[j >> 1][(j & 1) * 2]);
                        if (nprod >= 2)
                            mma16816(acc[mt][j], af[mt], &bl[j >> 1][(j & 1) * 2]);
                    }
                if (nprod >= 3) {
                    #pragma unroll
                    for (int mt = 0; mt < 4; mt++) {
                        uint32_t off = (uint32_t)(wm + mt * 16 + a_row) * (LDT * 2)
                                     + (k0 + a_col) * 2;
                        ldm4(af[mt], base + TILEB_A + off);
                    }
                    #pragma unroll
                    for (int mt = 0; mt < 4; mt++)
                        #pragma unroll
                        for (int j = 0; j < NJ; j++)
                            mma16816(acc[mt][j], af[mt], &bh[j >> 1][(j & 1) * 2]);
                }
            }
        }
    };

    issue(0);
    for (int kt = 0; kt < NCHK; kt++) {
        cp_wait<0>();
        __syncthreads();
        if (kt + 1 < NCHK) issue(kt + 1);
        compute(kt);
    }

    if (A.Ch) {
        #pragma unroll
        for (int mt = 0; mt < 4; mt++) {
            #pragma unroll
            for (int j = 0; j < NJ; j++) {
                int row = bm + wm + mt * 16 + (lane >> 2);
                int col = bn + wn + j * 8 + (lane & 3) * 2;
                *reinterpret_cast<__half2*>(A.Ch + (size_t)row * DD + col)
                    = __floats2half2_rn(acc[mt][j][0], acc[mt][j][1]);
                *reinterpret_cast<__half2*>(A.Ch + (size_t)(row + 8) * DD + col)
                    = __floats2half2_rn(acc[mt][j][2], acc[mt][j][3]);
            }
        }
    } else {
        #pragma unroll
        for (int mt = 0; mt < 4; mt++) {
            #pragma unroll
            for (int j = 0; j < NJ; j++) {
                int row = bm + wm + mt * 16 + (lane >> 2);
                int col = bn + wn + j * 8 + (lane & 3) * 2;
                *reinterpret_cast<float2*>(A.C + (size_t)row * DD + col)
                    = make_float2(acc[mt][j][0], acc[mt][j][1]);
                *reinterpret_cast<float2*>(A.C + (size_t)(row + 8) * DD + col)
                    = make_float2(acc[mt][j][2], acc[mt][j][3]);
            }
        }
    }

    if (A.vsum) {
        int b = bm / SS;
        #pragma unroll
        for (int j = 0; j < NJ; j++) {
            float s0 = 0.0f, s1 = 0.0f;
            #pragma unroll
            for (int mt = 0; mt < 4; mt++) {
                s0 += acc[mt][j][0] + acc[mt][j][2];
                s1 += acc[mt][j][1] + acc[mt][j][3];
            }
            #pragma unroll
            for (int o = 4; o < 32; o <<= 1) {
                s0 += __shfl_xor_sync(0xFFFFFFFFu, s0, o);
                s1 += __shfl_xor_sync(0xFFFFFFFFu, s1, o);
            }
            if (lane < 4) {
                int col = bn + wn + j * 8 + lane * 2;
                atomicAdd(&A.vsum[b * DD + col], s0);
                atomicAdd(&A.vsum[b * DD + col + 1], s1);
            }
        }
    }
}

// ---------------------------------------------------------------------------
// fp32 -> (f16 hi, f16 lo) splits
// ---------------------------------------------------------------------------
__device__ __forceinline__ void split4h(float4 v, ushort4& h, ushort4& l) {
    __half b;
    b = __float2half(v.x); h.x = __half_as_ushort(b);
    l.x = __half_as_ushort(__float2half(v.x - __half2float(b)));
    b = __float2half(v.y); h.y = __half_as_ushort(b);
    l.y = __half_as_ushort(__float2half(v.y - __half2float(b)));
    b = __float2half(v.z); h.z = __half_as_ushort(b);
    l.z = __half_as_ushort(__float2half(v.z - __half2float(b)));
    b = __float2half(v.w); h.w = __half_as_ushort(b);
    l.w = __half_as_ushort(__float2half(v.w - __half2float(b)));
}

struct SplitN {
    const float4* x[4];
    ushort4* hi[4];
    ushort4* lo[4];
    int zero_vsum;
};
__global__ void split_multi(SplitN a, int n4)
{
    int w = blockIdx.y;
    int i = blockIdx.x * blockDim.x + threadIdx.x;
    if (a.zero_vsum && w == 0 && i < BB * DD) g_vsum[i] = 0.0f;
    if (i >= n4) return;
    ushort4 h, l;
    split4h(a.x[w][i], h, l);
    a.hi[w][i] = h;
    if (a.lo[w]) a.lo[w][i] = l;
}

// ---------------------------------------------------------------------------
// Fused attention. Blocks [0,NBLK_GLB): global rows. Then mid rows,
// 8 lanes per item, 4 items per warp. v is f16 (g_vp).
// ---------------------------------------------------------------------------
__device__ __forceinline__ void store_hl(size_t off, float v) {
    __half h = __float2half(v);
    g_ah[off] = h;
    g_al[off] = __float2half(v - __half2float(h));
}

__global__ __launch_bounds__(256, 3) void attn_kernel(const int* __restrict__ idx)
{
    if (blockIdx.x >= NBLK_GLB) {
        // ------------------- middle rows -------------------
        int lane = threadIdx.x & 31;
        int grp = lane >> 3;
        int d = lane & 7;
        int w = (blockIdx.x - NBLK_GLB) * 8 + (threadIdx.x >> 5);
        if (w * 4 >= N_ITEMS) return;
        int item = w * 4 + grp;

        int i = item % SMID;
        int h = (item / SMID) % NH;
        int b = item / (SMID * NH);
        int s = i + GG;

        const __half* qrow = g_qp + ((size_t)b * SS + s) * DD + h * DK + d * 8;
        uint4 qv = *reinterpret_cast<const uint4*>(qrow);
        float2 qf0 = __half22float2(*reinterpret_cast<__half2*>(&qv.x));
        float2 qf1 = __half22float2(*reinterpret_cast<__half2*>(&qv.y));
        float2 qf2 = __half22float2(*reinterpret_cast<__half2*>(&qv.z));
        float2 qf3 = __half22float2(*reinterpret_cast<__half2*>(&qv.w));

        int cols[NIDX];
        #pragma unroll
        for (int j = 0; j < NIDX; j++) cols[j] = idx[i * NIDX + j];

        // all k and v loads issued up front: 12 independent 16B loads
        uint4 kv[NIDX], vv[NIDX];
        #pragma unroll
        for (int j = 0; j < NIDX; j++) {
            size_t roff = ((size_t)b * SS + cols[j]) * DD + h * DK + d * 8;
            kv[j] = *reinterpret_cast<const uint4*>(g_kp + roff);
            vv[j] = *reinterpret_cast<const uint4*>(g_vp + roff);
        }

        float sc[NIDX];
        #pragma unroll
        for (int j = 0; j < NIDX; j++) {
            float2 k0 = __half22float2(*reinterpret_cast<__half2*>(&kv[j].x));
            float2 k1 = __half22float2(*reinterpret_cast<__half2*>(&kv[j].y));
            float2 k2 = __half22float2(*reinterpret_cast<__half2*>(&kv[j].z));
            float2 k3 = __half22float2(*reinterpret_cast<__half2*>(&kv[j].w));
            float p = qf0.x * k0.x + qf0.y * k0.y
                    + qf1.x * k1.x + qf1.y * k1.y
                    + qf2.x * k2.x + qf2.y * k2.y
                    + qf3.x * k3.x + qf3.y * k3.y;
            p += __shfl_xor_sync(0xFFFFFFFFu, p, 1);
            p += __shfl_xor_sync(0xFFFFFFFFu, p, 2);
            p += __shfl_xor_sync(0xFFFFFFFFu, p, 4);
            sc[j] = p;
        }

        float wgt[NIDX];
        float denom = (float)SS;
        #pragma unroll
        for (int j = 0; j < NIDX; j++) {
            bool dup = false;
            #pragma unroll
            for (int jj = 0; jj < NIDX; jj++)
                if (jj < j) dup = dup || (cols[jj] == cols[j]);
            float wv = dup ? 0.0f : (expf(sc[j] * 0.125f) - 1.0f);
            wgt[j] = wv;
            denom += wv;
        }

        const float* vs = g_vsum + b * DD + h * DV + d * 8;
        float4 o0 = *reinterpret_cast<const float4*>(vs);
        float4 o1 = *reinterpret_cast<const float4*>(vs + 4);
        #pragma unroll
        for (int j = 0; j < NIDX; j++) {
            float2 a0 = __half22float2(*reinterpret_cast<__half2*>(&vv[j].x));
            float2 a1 = __half22float2(*reinterpret_cast<__half2*>(&vv[j].y));
            float2 a2 = __half22float2(*reinterpret_cast<__half2*>(&vv[j].z));
            float2 a3 = __half22float2(*reinterpret_cast<__half2*>(&vv[j].w));
            o0.x = fmaf(wgt[j], a0.x, o0.x); o0.y = fmaf(wgt[j], a0.y, o0.y);
            o0.z = fmaf(wgt[j], a1.x, o0.z); o0.w = fmaf(wgt[j], a1.y, o0.w);
            o1.x = fmaf(wgt[j], a2.x, o1.x); o1.y = fmaf(wgt[j], a2.y, o1.y);
            o1.z = fmaf(wgt[j], a3.x, o1.z); o1.w = fmaf(wgt[j], a3.y, o1.w);
        }
        float inv = 1.0f / denom;
        float of[8] = {o0.x * inv, o0.y * inv, o0.z * inv, o0.w * inv,
                       o1.x * inv, o1.y * inv, o1.z * inv, o1.w * inv};

        __half2 hi[4], lo[4];
        #pragma unroll
        for (int e = 0; e < 4; e++) {
            __half h0 = __float2half(of[2 * e]);
            __half h1 = __float2half(of[2 * e + 1]);
            hi[e] = __halves2half2(h0, h1);
            lo[e] = __halves2half2(
                __float2half(of[2 * e] - __half2float(h0)),
                __float2half(of[2 * e + 1] - __half2float(h1)));
        }
        size_t base = ((size_t)b * SS + s) * DD + h * DV + d * 8;
        *reinterpret_cast<uint4*>(g_ah + base) = *reinterpret_cast<uint4*>(hi);
        *reinterpret_cast<uint4*>(g_al + base) = *reinterpret_cast<uint4*>(lo);
    } else {
        // ------------------- global rows -------------------
        int item = blockIdx.x;
        int r = item % 2;
        int h = (item / 2) % NH;
        int b = item / (2 * NH);
        int s = r ? (SS - 1) : 0;
        int tid = threadIdx.x;

        __shared__ float sc[SS];
        __shared__ float qs[DK];
        __shared__ float red[256];

        const __half* qrow = g_qp + ((size_t)b * SS + s) * DD + h * DK;
        if (tid < DK) qs[tid] = __half2float(qrow[tid]);
        __syncthreads();

        for (int t = tid; t < SS; t += 256) {
            const __half* krow = g_kp + ((size_t)b * SS + t) * DD + h * DK;
            float p = 0.0f;
            #pragma unroll
            for (int dd = 0; dd < DK; dd++) p = fmaf(qs[dd], __half2float(krow[dd]), p);
            sc[t] = p * 0.125f;
        }
        __syncthreads();

        float m = -1e30f;
        for (int t = tid; t < SS; t += 256) m = fmaxf(m, sc[t]);
        red[tid] = m; __syncthreads();
        for (int o = 128; o > 0; o >>= 1) {
            if (tid < o) red[tid] = fmaxf(red[tid], red[tid + o]);
            __syncthreads();
        }
        m = red[0];
        __syncthreads();

        float sum = 0.0f;
        for (int t = tid; t < SS; t += 256) {
            float e = expf(sc[t] - m);
            sc[t] = e;
            sum += e;
        }
        red[tid] = sum; __syncthreads();
        for (int o = 128; o > 0; o >>= 1) {
            if (tid < o) red[tid] += red[tid + o];
            __syncthreads();
        }
        float inv = 1.0f / red[0];
        __syncthreads();

        int dv = tid % DV;
        int chunk = tid / DV;
        float acc = 0.0f;
        const __half* vb = g_vp + (size_t)b * SS * DD + h * DV + dv;
        for (int t = chunk * (SS / 4); t < (chunk + 1) * (SS / 4); t++)
            acc = fmaf(sc[t], __half2float(vb[(size_t)t * DD]), acc);
        red[tid] = acc; __syncthreads();
        if (tid < DV) {
            float o = (red[dv] + red[DV + dv] + red[2 * DV + dv] + red[3 * DV + dv]) * inv;
            store_hl(((size_t)b * SS + s) * DD + h * DV + dv, o);
        }
    }
}

// ---------------------------------------------------------------------------
extern "C" void kernel_launch(void* const* d_in, const int* in_sizes, int n_in,
                              void* d_out, int out_size)
{
    const float* Q  = (const float*)d_in[0];
    const float* K  = (const float*)d_in[1];
    const float* V  = (const float*)d_in[2];
    const float* Wq = (const float*)d_in[3];
    const float* Wk = (const float*)d_in[4];
    const float* Wv = (const float*)d_in[5];
    const float* Wo = (const float*)d_in[6];
    const int*   idx = (const int*)d_in[7];
    float* out = (float*)d_out;

    float* pvs;
    cudaGetSymbolAddress((void**)&pvs, g_vsum);

    __half *qp, *kp, *vp, *qh, *kh, *vh, *ah, *al;
    __half *wqh, *wkh, *wvh, *wvl, *woh, *wol;
    cudaGetSymbolAddress((void**)&qp, g_qp);
    cudaGetSymbolAddress((void**)&kp, g_kp);
    cudaGetSymbolAddress((void**)&vp, g_vp);
    cudaGetSymbolAddress((void**)&qh, g_qh);
    cudaGetSymbolAddress((void**)&kh, g_kh);
    cudaGetSymbolAddress((void**)&vh, g_vh);
    cudaGetSymbolAddress((void**)&ah, g_ah);  cudaGetSymbolAddress((void**)&al, g_al);
    cudaGetSymbolAddress((void**)&wqh, g_wqh);
    cudaGetSymbolAddress((void**)&wkh, g_wkh);
    cudaGetSymbolAddress((void**)&wvh, g_wvh); cudaGetSymbolAddress((void**)&wvl, g_wvl);
    cudaGetSymbolAddress((void**)&woh, g_woh); cudaGetSymbolAddress((void**)&wol, g_wol);

    constexpr int SMEM128 = NSTG * (2 * 128 * LDT * 2 + 2 * 128 * LDT * 2);
    constexpr int SMEM64  = NSTG * (2 * 128 * LDT * 2 + 2 * 64 * LDT * 2);
    cudaFuncSetAttribute(gemm_mma<128>, cudaFuncAttributeMaxDynamicSharedMemorySize, SMEM128);
    cudaFuncSetAttribute(gemm_mma<64>,  cudaFuncAttributeMaxDynamicSharedMemorySize, SMEM64);

    const int n4_big = MROWS * DD / 4;
    const int n4_w   = DD * DD / 4;
    const int bl_big = (n4_big + 255) / 256;
    const int bl_w   = (n4_w + 255) / 256;

    SplitN si;
    si.x[0] = (const float4*)Q; si.hi[0] = (ushort4*)qh; si.lo[0] = nullptr;
    si.x[1] = (const float4*)K; si.hi[1] = (ushort4*)kh; si.lo[1] = nullptr;
    si.x[2] = (const float4*)V; si.hi[2] = (ushort4*)vh; si.lo[2] = nullptr;
    si.x[3] = si.x[0]; si.hi[3] = si.hi[0]; si.lo[3] = nullptr;
    si.zero_vsum = 0;
    split_multi<<<dim3(bl_big, 3), 256>>>(si, n4_big);

    SplitN sw;
    sw.x[0] = (const float4*)Wq; sw.hi[0] = (ushort4*)wqh; sw.lo[0] = nullptr;
    sw.x[1] = (const float4*)Wk; sw.hi[1] = (ushort4*)wkh; sw.lo[1] = nullptr;
    sw.x[2] = (const float4*)Wv; sw.hi[2] = (ushort4*)wvh; sw.lo[2] = (ushort4*)wvl;
    sw.x[3] = (const float4*)Wo; sw.hi[3] = (ushort4*)woh; sw.lo[3] = (ushort4*)wol;
    sw.zero_vsum = 1;
    split_multi<<<dim3(bl_w, 4), 256>>>(sw, n4_w);

    // V slice first (heaviest: 2 products + vsum).
    Gemm3 g3;
    g3.g[0] = {vh, nullptr, wvh, wvl, nullptr, vp, pvs, 2};
    g3.g[1] = {qh, nullptr, wqh, nullptr, nullptr, qp, nullptr, 1};
    g3.g[2] = {kh, nullptr, wkh, nullptr, nullptr, kp, nullptr, 1};
    gemm_mma<128><<<dim3(DD / 128, MROWS / BM, 3), 256, SMEM128>>>(g3);

    attn_kernel<<<NBLK_GLB + NBLK_MID, 256>>>(idx);

    Gemm3 go;
    go.g[0] = {ah, al, woh, wol, out, nullptr, nullptr, 3};
    go.g[1] = go.g[0];
    go.g[2] = go.g[0];
    gemm_mma<64><<<dim3(DD / 64, MROWS / BM, 1), 256, SMEM64>>>(go);
}

// round 13
// speedup vs baseline: 1.1345x; 1.0029x over previous
#include <cuda_runtime.h>
#include <cuda_fp16.h>
#include <cstdint>
#include <math.h>

// Problem constants
#define BB 2
#define SS 2048
#define DD 768
#define NH 12
#define DK 64
#define DV 64
#define GG 1
#define NIDX 6
#define SMID (SS - 2*GG)
#define MROWS (BB * SS)

// GEMM tiling
#define BM 128
#define BKK 32
#define NCHK (DD / BKK)
#define LDT 40
#define NSTG 2

// Fused attention kernel geometry: global blocks FIRST, then mid blocks.
#define N_ITEMS (BB * NH * SMID)                  // 49104 (divisible by 4)
#define N_MWARPS (N_ITEMS / 4)                    // 12276
#define NBLK_MID ((N_MWARPS + 7) / 8)             // 1535
#define NBLK_GLB (BB * NH * 2)                    // 48

// ---------------------------------------------------------------------------
// Scratch
// ---------------------------------------------------------------------------
__device__ float g_vsum[BB * DD];

__device__ __half g_qp[MROWS * DD];
__device__ __half g_kp[MROWS * DD];
__device__ __half g_vp[MROWS * DD];
__device__ __half g_qh[MROWS * DD];
__device__ __half g_kh[MROWS * DD];
__device__ __half g_vh[MROWS * DD];
__device__ __half g_ah[MROWS * DD], g_al[MROWS * DD];
__device__ __half g_wqh[DD * DD];
__device__ __half g_wkh[DD * DD];
__device__ __half g_wvh[DD * DD], g_wvl[DD * DD];
__device__ __half g_woh[DD * DD], g_wol[DD * DD];

// ---------------------------------------------------------------------------
// PTX helpers (portable sm_80+ ISA)
// ---------------------------------------------------------------------------
__device__ __forceinline__ uint32_t smem_u32(const void* p) {
    uint32_t a;
    asm("{ .reg .u64 t; cvta.to.shared.u64 t, %1; cvt.u32.u64 %0, t; }"
        : "=r"(a) : "l"(p));
    return a;
}
__device__ __forceinline__ void cp_async16(uint32_t dst, const void* src) {
    asm volatile("cp.async.cg.shared.global [%0], [%1], 16;"
                 :: "r"(dst), "l"(src) : "memory");
}
__device__ __forceinline__ void cp_commit() {
    asm volatile("cp.async.commit_group;" ::: "memory");
}
template <int N>
__device__ __forceinline__ void cp_wait() {
    asm volatile("cp.async.wait_group %0;" :: "n"(N) : "memory");
}
__device__ __forceinline__ void ldm4(uint32_t* r, uint32_t addr) {
    asm volatile("ldmatrix.sync.aligned.m8n8.x4.shared.b16 {%0,%1,%2,%3}, [%4];"
                 : "=r"(r[0]), "=r"(r[1]), "=r"(r[2]), "=r"(r[3]) : "r"(addr));
}
__device__ __forceinline__ void mma16816(float* c, const uint32_t* a, const uint32_t* b) {
    asm volatile(
        "mma.sync.aligned.m16n8k16.row.col.f32.f16.f16.f32 "
        "{%0,%1,%2,%3}, {%4,%5,%6,%7}, {%8,%9}, {%0,%1,%2,%3};"
        : "+f"(c[0]), "+f"(c[1]), "+f"(c[2]), "+f"(c[3])
        : "r"(a[0]), "r"(a[1]), "r"(a[2]), "r"(a[3]), "r"(b[0]), "r"(b[1]));
}

struct GemmArgs {
    const __half *Ah, *Al, *Bh, *Bl;
    float* C;
    __half* Ch;
    float* vsum;
    int nprod;        // 1: Ah*Bh ; 2: + Ah*Bl ; 3: + Al*Bh
};
struct Gemm3 { GemmArgs g[3]; };

// ---------------------------------------------------------------------------
// GEMM (unchanged)
// ---------------------------------------------------------------------------
template <int BNT>
__global__ __launch_bounds__(256, 2) void gemm_mma(Gemm3 ga)
{
    constexpr int WNT = BNT / 4;
    constexpr int NJ = WNT / 8;
    constexpr int TILEB_A = 128 * LDT * 2;
    constexpr int TILEB_B = BNT * LDT * 2;
    constexpr int STAGEB = 2 * TILEB_A + 2 * TILEB_B;
    constexpr int NCHUNK = (2 * 128 + 2 * BNT) * 4;
    constexpr int PER_THR = NCHUNK / 256;

    extern __shared__ char smem[];
    const GemmArgs& A = ga.g[blockIdx.z];
    const int nprod = A.nprod;
    const uint32_t sb = smem_u32(smem);
    const int tid = threadIdx.x;
    const int wid = tid >> 5;
    const int lane = tid & 31;
    const int bm = blockIdx.y * BM;
    const int bn = blockIdx.x * BNT;
    const int wm = (wid >> 2) * 64;
    const int wn = (wid & 3) * WNT;

    float acc[4][NJ][4];
    #pragma unroll
    for (int i = 0; i < 4; i++)
        #pragma unroll
        for (int j = 0; j < NJ; j++)
            #pragma unroll
            for (int e = 0; e < 4; e++) acc[i][j][e] = 0.0f;

    auto issue = [&](int kt) {
        const int st = kt % NSTG;
        #pragma unroll
        for (int q8 = 0; q8 < PER_THR; q8++) {
            int q = tid + q8 * 256;
            if (q < 1024) {
                int t = q >> 9;
                if (t == 1 && nprod < 3) continue;
                int r = (q >> 2) & 127;
                int c = q & 3;
                const __half* src = (t ? A.Al : A.Ah)
                                    + (size_t)(bm + r) * DD + kt * BKK + c * 8;
                uint32_t dst = sb + st * STAGEB + t * TILEB_A + r * (LDT * 2) + c * 16;
                cp_async16(dst, src);
            } else {
                int q2 = q - 1024;
                int t = q2 / (BNT * 4);
                if (t == 1 && nprod < 2) continue;
                int r = (q2 >> 2) % BNT;
                int c = q2 & 3;
                const __half* src = (t ? A.Bl : A.Bh)
                                    + (size_t)(bn + r) * DD + kt * BKK + c * 8;
                uint32_t dst = sb + st * STAGEB + 2 * TILEB_A + t * TILEB_B
                             + r * (LDT * 2) + c * 16;
                cp_async16(dst, src);
            }
        }
        cp_commit();
    };

    const int a_row = lane & 15;
    const int a_col = (lane >> 4) * 8;
    const int b_row = (lane & 7) + ((lane >> 4) << 3);
    const int b_col = ((lane >> 3) & 1) * 8;

    auto compute = [&](int kt) {
        const uint32_t base = sb + (kt % NSTG) * STAGEB;
        #pragma unroll
        for (int ks = 0; ks < 2; ks++) {
            const int k0 = ks * 16;
            uint32_t bh[NJ / 2][4], bl[NJ / 2][4];
            #pragma unroll
            for (int nh = 0; nh < NJ / 2; nh++) {
                uint32_t off = (uint32_t)(wn + nh * 16 + b_row) * (LDT * 2)
                             + (k0 + b_col) * 2;
                ldm4(bh[nh], base + 2 * TILEB_A + off);
                if (nprod >= 2)
                    ldm4(bl[nh], base + 2 * TILEB_A + TILEB_B + off);
            }
            uint32_t af[4][4];
            #pragma unroll
            for (int mt = 0; mt < 4; mt++) {
                uint32_t off = (uint32_t)(wm + mt * 16 + a_row) * (LDT * 2)
                             + (k0 + a_col) * 2;
                ldm4(af[mt], base + off);
            }
            if constexpr (NJ == 2) {
                uint32_t alf[4][4];
                if (nprod >= 3) {
                    #pragma unroll
                    for (int mt = 0; mt < 4; mt++) {
                        uint32_t off = (uint32_t)(wm + mt * 16 + a_row) * (LDT * 2)
                                     + (k0 + a_col) * 2;
                        ldm4(alf[mt], base + TILEB_A + off);
                    }
                }
                #pragma unroll
                for (int mt = 0; mt < 4; mt++)
                    #pragma unroll
                    for (int j = 0; j < NJ; j++) {
                        mma16816(acc[mt][j], af[mt], &bh[j >> 1][(j & 1) * 2]);
                        if (nprod >= 2)
                            mma16816(acc[mt][j], af[mt], &bl[j >> 1][(j & 1) * 2]);
                        if (nprod >= 3)
                            mma16816(acc[mt][j], alf[mt], &bh[j >> 1][(j & 1) * 2]);
                    }
            } else {
                #pragma unroll
                for (int mt = 0; mt < 4; mt++)
                    #pragma unroll
                    for (int j = 0; j < NJ; j++) {
                        mma16816(acc[mt][j], af[mt], &bh[j >> 1][(j & 1) * 2]);
                        if (nprod >= 2)
                            mma16816(acc[mt][j], af[mt], &bl[j >> 1][(j & 1) * 2]);
                    }
                if (nprod >= 3) {
                    #pragma unroll
                    for (int mt = 0; mt < 4; mt++) {
                        uint32_t off = (uint32_t)(wm + mt * 16 + a_row) * (LDT * 2)
                                     + (k0 + a_col) * 2;
                        ldm4(af[mt], base + TILEB_A + off);
                    }
                    #pragma unroll
                    for (int mt = 0; mt < 4; mt++)
                        #pragma unroll
                        for (int j = 0; j < NJ; j++)
                            mma16816(acc[mt][j], af[mt], &bh[j >> 1][(j & 1) * 2]);
                }
            }
        }
    };

    issue(0);
    for (int kt = 0; kt < NCHK; kt++) {
        cp_wait<0>();
        __syncthreads();
        if (kt + 1 < NCHK) issue(kt + 1);
        compute(kt);
    }

    if (A.Ch) {
        #pragma unroll
        for (int mt = 0; mt < 4; mt++) {
            #pragma unroll
            for (int j = 0; j < NJ; j++) {
                int row = bm + wm + mt * 16 + (lane >> 2);
                int col = bn + wn + j * 8 + (lane & 3) * 2;
                *reinterpret_cast<__half2*>(A.Ch + (size_t)row * DD + col)
                    = __floats2half2_rn(acc[mt][j][0], acc[mt][j][1]);
                *reinterpret_cast<__half2*>(A.Ch + (size_t)(row + 8) * DD + col)
                    = __floats2half2_rn(acc[mt][j][2], acc[mt][j][3]);
            }
        }
    } else {
        #pragma unroll
        for (int mt = 0; mt < 4; mt++) {
            #pragma unroll
            for (int j = 0; j < NJ; j++) {
                int row = bm + wm + mt * 16 + (lane >> 2);
                int col = bn + wn + j * 8 + (lane & 3) * 2;
                *reinterpret_cast<float2*>(A.C + (size_t)row * DD + col)
                    = make_float2(acc[mt][j][0], acc[mt][j][1]);
                *reinterpret_cast<float2*>(A.C + (size_t)(row + 8) * DD + col)
                    = make_float2(acc[mt][j][2], acc[mt][j][3]);
            }
        }
    }

    if (A.vsum) {
        int b = bm / SS;
        #pragma unroll
        for (int j = 0; j < NJ; j++) {
            float s0 = 0.0f, s1 = 0.0f;
            #pragma unroll
            for (int mt = 0; mt < 4; mt++) {
                s0 += acc[mt][j][0] + acc[mt][j][2];
                s1 += acc[mt][j][1] + acc[mt][j][3];
            }
            #pragma unroll
            for (int o = 4; o < 32; o <<= 1) {
                s0 += __shfl_xor_sync(0xFFFFFFFFu, s0, o);
                s1 += __shfl_xor_sync(0xFFFFFFFFu, s1, o);
            }
            if (lane < 4) {
                int col = bn + wn + j * 8 + lane * 2;
                atomicAdd(&A.vsum[b * DD + col], s0);
                atomicAdd(&A.vsum[b * DD + col + 1], s1);
            }
        }
    }
}

// ---------------------------------------------------------------------------
// fp32 -> (f16 hi, f16 lo) splits
// ---------------------------------------------------------------------------
__device__ __forceinline__ void split4h(float4 v, ushort4& h, ushort4& l) {
    __half b;
    b = __float2half(v.x); h.x = __half_as_ushort(b);
    l.x = __half_as_ushort(__float2half(v.x - __half2float(b)));
    b = __float2half(v.y); h.y = __half_as_ushort(b);
    l.y = __half_as_ushort(__float2half(v.y - __half2float(b)));
    b = __float2half(v.z); h.z = __half_as_ushort(b);
    l.z = __half_as_ushort(__float2half(v.z - __half2float(b)));
    b = __float2half(v.w); h.w = __half_as_ushort(b);
    l.w = __half_as_ushort(__float2half(v.w - __half2float(b)));
}

struct SplitN {
    const float4* x[4];
    ushort4* hi[4];
    ushort4* lo[4];
    int zero_vsum;
};
__global__ void split_multi(SplitN a, int n4)
{
    int w = blockIdx.y;
    int i = blockIdx.x * blockDim.x + threadIdx.x;
    if (a.zero_vsum && w == 0 && i < BB * DD) g_vsum[i] = 0.0f;
    if (i >= n4) return;
    ushort4 h, l;
    split4h(a.x[w][i], h, l);
    a.hi[w][i] = h;
    if (a.lo[w]) a.lo[w][i] = l;
}

// ---------------------------------------------------------------------------
// Fused attention. Blocks [0,NBLK_GLB): global rows. Then mid rows,
// 8 lanes per item, 4 items per warp, half2 arithmetic throughout.
// ---------------------------------------------------------------------------
__device__ __forceinline__ void store_hl(size_t off, float v) {
    __half h = __float2half(v);
    g_ah[off] = h;
    g_al[off] = __float2half(v - __half2float(h));
}

__global__ __launch_bounds__(256, 3) void attn_kernel(const int* __restrict__ idx)
{
    if (blockIdx.x >= NBLK_GLB) {
        // ------------------- middle rows -------------------
        int lane = threadIdx.x & 31;
        int grp = lane >> 3;
        int d = lane & 7;
        int w = (blockIdx.x - NBLK_GLB) * 8 + (threadIdx.x >> 5);
        if (w * 4 >= N_ITEMS) return;
        int item = w * 4 + grp;

        int i = item % SMID;
        int h = (item / SMID) % NH;
        int b = item / (SMID * NH);
        int s = i + GG;

        // idx row: 24B, 8-byte aligned -> 3x int2
        const int2* ip = reinterpret_cast<const int2*>(idx + i * NIDX);
        int2 c0 = ip[0], c1 = ip[1], c2 = ip[2];
        int cols[NIDX] = {c0.x, c0.y, c1.x, c1.y, c2.x, c2.y};

        uint32_t rowq = ((unsigned)(b * SS + s) * DD + h * DK + d * 8) * 2;
        uint4 qv = *reinterpret_cast<const uint4*>(
            reinterpret_cast<const char*>(g_qp) + rowq);
        const __half2* q2 = reinterpret_cast<const __half2*>(&qv);

        // all k and v loads issued up front: 12 independent 16B loads
        uint4 kv[NIDX], vv[NIDX];
        #pragma unroll
        for (int j = 0; j < NIDX; j++) {
            uint32_t ro = ((unsigned)(b * SS + cols[j]) * DD + h * DK + d * 8) * 2;
            kv[j] = *reinterpret_cast<const uint4*>(
                reinterpret_cast<const char*>(g_kp) + ro);
            vv[j] = *reinterpret_cast<const uint4*>(
                reinterpret_cast<const char*>(g_vp) + ro);
        }

        float sc[NIDX];
        #pragma unroll
        for (int j = 0; j < NIDX; j++) {
            const __half2* k2 = reinterpret_cast<const __half2*>(&kv[j]);
            __half2 a2 = __hmul2(q2[0], k2[0]);
            a2 = __hfma2(q2[1], k2[1], a2);
            a2 = __hfma2(q2[2], k2[2], a2);
            a2 = __hfma2(q2[3], k2[3], a2);
            float2 pf = __half22float2(a2);
            float p = pf.x + pf.y;
            p += __shfl_xor_sync(0xFFFFFFFFu, p, 1);
            p += __shfl_xor_sync(0xFFFFFFFFu, p, 2);
            p += __shfl_xor_sync(0xFFFFFFFFu, p, 4);
            sc[j] = p;
        }

        // Dedupe: by idx construction (rand cols drawn from [1,S) excluding the
        // window band; windows strictly increasing), the only possible duplicate
        // is cols[j] == cols[0] (the leading global-0 column).
        float denom = (float)SS;
        __half2 w2[NIDX];
        #pragma unroll
        for (int j = 0; j < NIDX; j++) {
            bool dup = (j > 0) && (cols[j] == cols[0]);
            float wv = dup ? 0.0f : (__expf(sc[j] * 0.125f) - 1.0f);
            denom += wv;
            w2[j] = __half2half2(__float2half_rn(wv));
        }

        // v correction accumulated in half2 (error ~1e-3 abs on corr, /2048 at output)
        __half2 corr[4];
        {
            const __half2* v2 = reinterpret_cast<const __half2*>(&vv[0]);
            #pragma unroll
            for (int e = 0; e < 4; e++) corr[e] = __hmul2(w2[0], v2[e]);
        }
        #pragma unroll
        for (int j = 1; j < NIDX; j++) {
            const __half2* v2 = reinterpret_cast<const __half2*>(&vv[j]);
            #pragma unroll
            for (int e = 0; e < 4; e++) corr[e] = __hfma2(w2[j], v2[e], corr[e]);
        }

        const float* vs = g_vsum + b * DD + h * DV + d * 8;
        float4 u0 = *reinterpret_cast<const float4*>(vs);
        float4 u1 = *reinterpret_cast<const float4*>(vs + 4);
        float inv = 1.0f / denom;
        float2 cf0 = __half22float2(corr[0]);
        float2 cf1 = __half22float2(corr[1]);
        float2 cf2 = __half22float2(corr[2]);
        float2 cf3 = __half22float2(corr[3]);
        float of[8] = {(u0.x + cf0.x) * inv, (u0.y + cf0.y) * inv,
                       (u0.z + cf1.x) * inv, (u0.w + cf1.y) * inv,
                       (u1.x + cf2.x) * inv, (u1.y + cf2.y) * inv,
                       (u1.z + cf3.x) * inv, (u1.w + cf3.y) * inv};

        __half2 hi[4], lo[4];
        #pragma unroll
        for (int e = 0; e < 4; e++) {
            __half h0 = __float2half(of[2 * e]);
            __half h1 = __float2half(of[2 * e + 1]);
            hi[e] = __halves2half2(h0, h1);
            lo[e] = __halves2half2(
                __float2half(of[2 * e] - __half2float(h0)),
                __float2half(of[2 * e + 1] - __half2float(h1)));
        }
        size_t base = ((size_t)b * SS + s) * DD + h * DV + d * 8;
        *reinterpret_cast<uint4*>(g_ah + base) = *reinterpret_cast<uint4*>(hi);
        *reinterpret_cast<uint4*>(g_al + base) = *reinterpret_cast<uint4*>(lo);
    } else {
        // ------------------- global rows -------------------
        int item = blockIdx.x;
        int r = item % 2;
        int h = (item / 2) % NH;
        int b = item / (2 * NH);
        int s = r ? (SS - 1) : 0;
        int tid = threadIdx.x;

        __shared__ float sc[SS];
        __shared__ float qs[DK];
        __shared__ float red[256];

        const __half* qrow = g_qp + ((size_t)b * SS + s) * DD + h * DK;
        if (tid < DK) qs[tid] = __half2float(qrow[tid]);
        __syncthreads();

        for (int t = tid; t < SS; t += 256) {
            const __half* krow = g_kp + ((size_t)b * SS + t) * DD + h * DK;
            float p = 0.0f;
            #pragma unroll
            for (int dd = 0; dd < DK; dd++) p = fmaf(qs[dd], __half2float(krow[dd]), p);
            sc[t] = p * 0.125f;
        }
        __syncthreads();

        float m = -1e30f;
        for (int t = tid; t < SS; t += 256) m = fmaxf(m, sc[t]);
        red[tid] = m; __syncthreads();
        for (int o = 128; o > 0; o >>= 1) {
            if (tid < o) red[tid] = fmaxf(red[tid], red[tid + o]);
            __syncthreads();
        }
        m = red[0];
        __syncthreads();

        float sum = 0.0f;
        for (int t = tid; t < SS; t += 256) {
            float e = __expf(sc[t] - m);
            sc[t] = e;
            sum += e;
        }
        red[tid] = sum; __syncthreads();
        for (int o = 128; o > 0; o >>= 1) {
            if (tid < o) red[tid] += red[tid + o];
            __syncthreads();
        }
        float inv = 1.0f / red[0];
        __syncthreads();

        int dv = tid % DV;
        int chunk = tid / DV;
        float acc = 0.0f;
        const __half* vb = g_vp + (size_t)b * SS * DD + h * DV + dv;
        for (int t = chunk * (SS / 4); t < (chunk + 1) * (SS / 4); t++)
            acc = fmaf(sc[t], __half2float(vb[(size_t)t * DD]), acc);
        red[tid] = acc; __syncthreads();
        if (tid < DV) {
            float o = (red[dv] + red[DV + dv] + red[2 * DV + dv] + red[3 * DV + dv]) * inv;
            store_hl(((size_t)b * SS + s) * DD + h * DV + dv, o);
        }
    }
}

// ---------------------------------------------------------------------------
extern "C" void kernel_launch(void* const* d_in, const int* in_sizes, int n_in,
                              void* d_out, int out_size)
{
    const float* Q  = (const float*)d_in[0];
    const float* K  = (const float*)d_in[1];
    const float* V  = (const float*)d_in[2];
    const float* Wq = (const float*)d_in[3];
    const float* Wk = (const float*)d_in[4];
    const float* Wv = (const float*)d_in[5];
    const float* Wo = (const float*)d_in[6];
    const int*   idx = (const int*)d_in[7];
    float* out = (float*)d_out;

    float* pvs;
    cudaGetSymbolAddress((void**)&pvs, g_vsum);

    __half *qp, *kp, *vp, *qh, *kh, *vh, *ah, *al;
    __half *wqh, *wkh, *wvh, *wvl, *woh, *wol;
    cudaGetSymbolAddress((void**)&qp, g_qp);
    cudaGetSymbolAddress((void**)&kp, g_kp);
    cudaGetSymbolAddress((void**)&vp, g_vp);
    cudaGetSymbolAddress((void**)&qh, g_qh);
    cudaGetSymbolAddress((void**)&kh, g_kh);
    cudaGetSymbolAddress((void**)&vh, g_vh);
    cudaGetSymbolAddress((void**)&ah, g_ah);  cudaGetSymbolAddress((void**)&al, g_al);
    cudaGetSymbolAddress((void**)&wqh, g_wqh);
    cudaGetSymbolAddress((void**)&wkh, g_wkh);
    cudaGetSymbolAddress((void**)&wvh, g_wvh); cudaGetSymbolAddress((void**)&wvl, g_wvl);
    cudaGetSymbolAddress((void**)&woh, g_woh); cudaGetSymbolAddress((void**)&wol, g_wol);

    constexpr int SMEM128 = NSTG * (2 * 128 * LDT * 2 + 2 * 128 * LDT * 2);
    constexpr int SMEM64  = NSTG * (2 * 128 * LDT * 2 + 2 * 64 * LDT * 2);
    cudaFuncSetAttribute(gemm_mma<128>, cudaFuncAttributeMaxDynamicSharedMemorySize, SMEM128);
    cudaFuncSetAttribute(gemm_mma<64>,  cudaFuncAttributeMaxDynamicSharedMemorySize, SMEM64);

    const int n4_big = MROWS * DD / 4;
    const int n4_w   = DD * DD / 4;
    const int bl_big = (n4_big + 255) / 256;
    const int bl_w   = (n4_w + 255) / 256;

    SplitN si;
    si.x[0] = (const float4*)Q; si.hi[0] = (ushort4*)qh; si.lo[0] = nullptr;
    si.x[1] = (const float4*)K; si.hi[1] = (ushort4*)kh; si.lo[1] = nullptr;
    si.x[2] = (const float4*)V; si.hi[2] = (ushort4*)vh; si.lo[2] = nullptr;
    si.x[3] = si.x[0]; si.hi[3] = si.hi[0]; si.lo[3] = nullptr;
    si.zero_vsum = 0;
    split_multi<<<dim3(bl_big, 3), 256>>>(si, n4_big);

    SplitN sw;
    sw.x[0] = (const float4*)Wq; sw.hi[0] = (ushort4*)wqh; sw.lo[0] = nullptr;
    sw.x[1] = (const float4*)Wk; sw.hi[1] = (ushort4*)wkh; sw.lo[1] = nullptr;
    sw.x[2] = (const float4*)Wv; sw.hi[2] = (ushort4*)wvh; sw.lo[2] = (ushort4*)wvl;
    sw.x[3] = (const float4*)Wo; sw.hi[3] = (ushort4*)woh; sw.lo[3] = (ushort4*)wol;
    sw.zero_vsum = 1;
    split_multi<<<dim3(bl_w, 4), 256>>>(sw, n4_w);

    Gemm3 g3;
    g3.g[0] = {vh, nullptr, wvh, wvl, nullptr, vp, pvs, 2};
    g3.g[1] = {qh, nullptr, wqh, nullptr, nullptr, qp, nullptr, 1};
    g3.g[2] = {kh, nullptr, wkh, nullptr, nullptr, kp, nullptr, 1};
    gemm_mma<128><<<dim3(DD / 128, MROWS / BM, 3), 256, SMEM128>>>(g3);

    attn_kernel<<<NBLK_GLB + NBLK_MID, 256>>>(idx);

    Gemm3 go;
    go.g[0] = {ah, al, woh, wol, out, nullptr, nullptr, 3};
    go.g[1] = go.g[0];
    go.g[2] = go.g[0];
    gemm_mma<64><<<dim3(DD / 64, MROWS / BM, 1), 256, SMEM64>>>(go);
}

// round 14
// speedup vs baseline: 1.1608x; 1.0232x over previous
#include <cuda_runtime.h>
#include <cuda_fp16.h>
#include <cstdint>
#include <math.h>

// Problem constants
#define BB 2
#define SS 2048
#define DD 768
#define NH 12
#define DK 64
#define DV 64
#define GG 1
#define NIDX 6
#define SMID (SS - 2*GG)
#define MROWS (BB * SS)

// GEMM tiling
#define BM 128
#define BKK 32
#define NCHK (DD / BKK)
#define LDT 40
#define NSTG 2

// Fused attention kernel geometry: global blocks FIRST, then persistent mid.
#define N_ITEMS (BB * NH * SMID)                  // 49104 (divisible by 4)
#define NBLK_MID 444                              // 148 SMs x 3 CTAs
#define NBLK_GLB (BB * NH * 2)                    // 48
#define MID_STRIDE (NBLK_MID * 8 * 4)             // items per loop round = 14208

// ---------------------------------------------------------------------------
// Scratch
// ---------------------------------------------------------------------------
__device__ float g_vsum[BB * DD];

__device__ __half g_qp[MROWS * DD];
__device__ __half g_kp[MROWS * DD];
__device__ __half g_vp[MROWS * DD];
__device__ __half g_qh[MROWS * DD];
__device__ __half g_kh[MROWS * DD];
__device__ __half g_vh[MROWS * DD];
__device__ __half g_ah[MROWS * DD], g_al[MROWS * DD];
__device__ __half g_wqh[DD * DD];
__device__ __half g_wkh[DD * DD];
__device__ __half g_wvh[DD * DD], g_wvl[DD * DD];
__device__ __half g_woh[DD * DD], g_wol[DD * DD];

// ---------------------------------------------------------------------------
// PTX helpers (portable sm_80+ ISA)
// ---------------------------------------------------------------------------
__device__ __forceinline__ uint32_t smem_u32(const void* p) {
    uint32_t a;
    asm("{ .reg .u64 t; cvta.to.shared.u64 t, %1; cvt.u32.u64 %0, t; }"
        : "=r"(a) : "l"(p));
    return a;
}
__device__ __forceinline__ void cp_async16(uint32_t dst, const void* src) {
    asm volatile("cp.async.cg.shared.global [%0], [%1], 16;"
                 :: "r"(dst), "l"(src) : "memory");
}
__device__ __forceinline__ void cp_commit() {
    asm volatile("cp.async.commit_group;" ::: "memory");
}
template <int N>
__device__ __forceinline__ void cp_wait() {
    asm volatile("cp.async.wait_group %0;" :: "n"(N) : "memory");
}
__device__ __forceinline__ void ldm4(uint32_t* r, uint32_t addr) {
    asm volatile("ldmatrix.sync.aligned.m8n8.x4.shared.b16 {%0,%1,%2,%3}, [%4];"
                 : "=r"(r[0]), "=r"(r[1]), "=r"(r[2]), "=r"(r[3]) : "r"(addr));
}
__device__ __forceinline__ void mma16816(float* c, const uint32_t* a, const uint32_t* b) {
    asm volatile(
        "mma.sync.aligned.m16n8k16.row.col.f32.f16.f16.f32 "
        "{%0,%1,%2,%3}, {%4,%5,%6,%7}, {%8,%9}, {%0,%1,%2,%3};"
        : "+f"(c[0]), "+f"(c[1]), "+f"(c[2]), "+f"(c[3])
        : "r"(a[0]), "r"(a[1]), "r"(a[2]), "r"(a[3]), "r"(b[0]), "r"(b[1]));
}

struct GemmArgs {
    const __half *Ah, *Al, *Bh, *Bl;
    float* C;
    __half* Ch;
    float* vsum;
    int nprod;        // 1: Ah*Bh ; 2: + Ah*Bl ; 3: + Al*Bh
};
struct Gemm3 { GemmArgs g[3]; };

// ---------------------------------------------------------------------------
// GEMM
// ---------------------------------------------------------------------------
template <int BNT>
__global__ __launch_bounds__(256, 2) void gemm_mma(Gemm3 ga)
{
    constexpr int WNT = BNT / 4;
    constexpr int NJ = WNT / 8;
    constexpr int TILEB_A = 128 * LDT * 2;
    constexpr int TILEB_B = BNT * LDT * 2;
    constexpr int STAGEB = 2 * TILEB_A + 2 * TILEB_B;
    constexpr int NCHUNK = (2 * 128 + 2 * BNT) * 4;
    constexpr int PER_THR = NCHUNK / 256;

    extern __shared__ char smem[];
    const GemmArgs& A = ga.g[blockIdx.z];
    const int nprod = A.nprod;
    const uint32_t sb = smem_u32(smem);
    const int tid = threadIdx.x;
    const int wid = tid >> 5;
    const int lane = tid & 31;
    const int bm = blockIdx.y * BM;
    const int bn = blockIdx.x * BNT;
    const int wm = (wid >> 2) * 64;
    const int wn = (wid & 3) * WNT;

    float acc[4][NJ][4];
    #pragma unroll
    for (int i = 0; i < 4; i++)
        #pragma unroll
        for (int j = 0; j < NJ; j++)
            #pragma unroll
            for (int e = 0; e < 4; e++) acc[i][j][e] = 0.0f;

    auto issue = [&](int kt) {
        const int st = kt % NSTG;
        #pragma unroll
        for (int q8 = 0; q8 < PER_THR; q8++) {
            int q = tid + q8 * 256;
            if (q < 1024) {
                int t = q >> 9;
                if (t == 1 && nprod < 3) continue;
                int r = (q >> 2) & 127;
                int c = q & 3;
                const __half* src = (t ? A.Al : A.Ah)
                                    + (size_t)(bm + r) * DD + kt * BKK + c * 8;
                uint32_t dst = sb + st * STAGEB + t * TILEB_A + r * (LDT * 2) + c * 16;
                cp_async16(dst, src);
            } else {
                int q2 = q - 1024;
                int t = q2 / (BNT * 4);
                if (t == 1 && nprod < 2) continue;
                int r = (q2 >> 2) % BNT;
                int c = q2 & 3;
                const __half* src = (t ? A.Bl : A.Bh)
                                    + (size_t)(bn + r) * DD + kt * BKK + c * 8;
                uint32_t dst = sb + st * STAGEB + 2 * TILEB_A + t * TILEB_B
                             + r * (LDT * 2) + c * 16;
                cp_async16(dst, src);
            }
        }
        cp_commit();
    };

    const int a_row = lane & 15;
    const int a_col = (lane >> 4) * 8;
    const int b_row = (lane & 7) + ((lane >> 4) << 3);
    const int b_col = ((lane >> 3) & 1) * 8;

    auto compute = [&](int kt) {
        const uint32_t base = sb + (kt % NSTG) * STAGEB;
        #pragma unroll
        for (int ks = 0; ks < 2; ks++) {
            const int k0 = ks * 16;
            uint32_t bh[NJ / 2][4], bl[NJ / 2][4];
            #pragma unroll
            for (int nh = 0; nh < NJ / 2; nh++) {
                uint32_t off = (uint32_t)(wn + nh * 16 + b_row) * (LDT * 2)
                             + (k0 + b_col) * 2;
                ldm4(bh[nh], base + 2 * TILEB_A + off);
                if (nprod >= 2)
                    ldm4(bl[nh], base + 2 * TILEB_A + TILEB_B + off);
            }
            uint32_t af[4][4];
            #pragma unroll
            for (int mt = 0; mt < 4; mt++) {
                uint32_t off = (uint32_t)(wm + mt * 16 + a_row) * (LDT * 2)
                             + (k0 + a_col) * 2;
                ldm4(af[mt], base + off);
            }
            if constexpr (NJ == 2) {
                uint32_t alf[4][4];
                if (nprod >= 3) {
                    #pragma unroll
                    for (int mt = 0; mt < 4; mt++) {
                        uint32_t off = (uint32_t)(wm + mt * 16 + a_row) * (LDT * 2)
                                     + (k0 + a_col) * 2;
                        ldm4(alf[mt], base + TILEB_A + off);
                    }
                }
                #pragma unroll
                for (int mt = 0; mt < 4; mt++)
                    #pragma unroll
                    for (int j = 0; j < NJ; j++) {
                        mma16816(acc[mt][j], af[mt], &bh[j >> 1][(j & 1) * 2]);
                        if (nprod >= 2)
                            mma16816(acc[mt][j], af[mt], &bl[j >> 1][(j & 1) * 2]);
                        if (nprod >= 3)
                            mma16816(acc[mt][j], alf[mt], &bh[j >> 1][(j & 1) * 2]);
                    }
            } else {
                #pragma unroll
                for (int mt = 0; mt < 4; mt++)
                    #pragma unroll
                    for (int j = 0; j < NJ; j++) {
                        mma16816(acc[mt][j], af[mt], &bh[j >> 1][(j & 1) * 2]);
                        if (nprod >= 2)
                            mma16816(acc[mt][j], af[mt], &bl[j >> 1][(j & 1) * 2]);
                    }
                if (nprod >= 3) {
                    #pragma unroll
                    for (int mt = 0; mt < 4; mt++) {
                        uint32_t off = (uint32_t)(wm + mt * 16 + a_row) * (LDT * 2)
                                     + (k0 + a_col) * 2;
                        ldm4(af[mt], base + TILEB_A + off);
                    }
                    #pragma unroll
                    for (int mt = 0; mt < 4; mt++)
                        #pragma unroll
                        for (int j = 0; j < NJ; j++)
                            mma16816(acc[mt][j], af[mt], &bh[j >> 1][(j & 1) * 2]);
                }
            }
        }
    };

    issue(0);
    for (int kt = 0; kt < NCHK; kt++) {
        cp_wait<0>();
        __syncthreads();
        if (kt + 1 < NCHK) issue(kt + 1);
        compute(kt);
    }

    if (A.Ch) {
        #pragma unroll
        for (int mt = 0; mt < 4; mt++) {
            #pragma unroll
            for (int j = 0; j < NJ; j++) {
                int row = bm + wm + mt * 16 + (lane >> 2);
                int col = bn + wn + j * 8 + (lane & 3) * 2;
                *reinterpret_cast<__half2*>(A.Ch + (size_t)row * DD + col)
                    = __floats2half2_rn(acc[mt][j][0], acc[mt][j][1]);
                *reinterpret_cast<__half2*>(A.Ch + (size_t)(row + 8) * DD + col)
                    = __floats2half2_rn(acc[mt][j][2], acc[mt][j][3]);
            }
        }
    } else {
        #pragma unroll
        for (int mt = 0; mt < 4; mt++) {
            #pragma unroll
            for (int j = 0; j < NJ; j++) {
                int row = bm + wm + mt * 16 + (lane >> 2);
                int col = bn + wn + j * 8 + (lane & 3) * 2;
                *reinterpret_cast<float2*>(A.C + (size_t)row * DD + col)
                    = make_float2(acc[mt][j][0], acc[mt][j][1]);
                *reinterpret_cast<float2*>(A.C + (size_t)(row + 8) * DD + col)
                    = make_float2(acc[mt][j][2], acc[mt][j][3]);
            }
        }
    }

    if (A.vsum) {
        int b = bm / SS;
        #pragma unroll
        for (int j = 0; j < NJ; j++) {
            float s0 = 0.0f, s1 = 0.0f;
            #pragma unroll
            for (int mt = 0; mt < 4; mt++) {
                s0 += acc[mt][j][0] + acc[mt][j][2];
                s1 += acc[mt][j][1] + acc[mt][j][3];
            }
            #pragma unroll
            for (int o = 4; o < 32; o <<= 1) {
                s0 += __shfl_xor_sync(0xFFFFFFFFu, s0, o);
                s1 += __shfl_xor_sync(0xFFFFFFFFu, s1, o);
            }
            if (lane < 4) {
                int col = bn + wn + j * 8 + lane * 2;
                atomicAdd(&A.vsum[b * DD + col], s0);
                atomicAdd(&A.vsum[b * DD + col + 1], s1);
            }
        }
    }
}

// ---------------------------------------------------------------------------
// fp32 -> (f16 hi, f16 lo) splits
// ---------------------------------------------------------------------------
__device__ __forceinline__ void split4h(float4 v, ushort4& h, ushort4& l) {
    __half b;
    b = __float2half(v.x); h.x = __half_as_ushort(b);
    l.x = __half_as_ushort(__float2half(v.x - __half2float(b)));
    b = __float2half(v.y); h.y = __half_as_ushort(b);
    l.y = __half_as_ushort(__float2half(v.y - __half2float(b)));
    b = __float2half(v.z); h.z = __half_as_ushort(b);
    l.z = __half_as_ushort(__float2half(v.z - __half2float(b)));
    b = __float2half(v.w); h.w = __half_as_ushort(b);
    l.w = __half_as_ushort(__float2half(v.w - __half2float(b)));
}

struct SplitN {
    const float4* x[4];
    ushort4* hi[4];
    ushort4* lo[4];
    int zero_vsum;
};
__global__ void split_multi(SplitN a, int n4)
{
    int w = blockIdx.y;
    int i = blockIdx.x * blockDim.x + threadIdx.x;
    if (a.zero_vsum && w == 0 && i < BB * DD) g_vsum[i] = 0.0f;
    if (i >= n4) return;
    ushort4 h, l;
    split4h(a.x[w][i], h, l);
    a.hi[w][i] = h;
    if (a.lo[w]) a.lo[w][i] = l;
}

// ---------------------------------------------------------------------------
// Fused attention. Blocks [0,NBLK_GLB): global rows. Then NBLK_MID persistent
// mid blocks; each warp strides over item groups (8 lanes/item, 4 items/warp).
// ---------------------------------------------------------------------------
__device__ __forceinline__ void store_hl(size_t off, float v) {
    __half h = __float2half(v);
    g_ah[off] = h;
    g_al[off] = __float2half(v - __half2float(h));
}

__global__ __launch_bounds__(256, 3) void attn_kernel(const int* __restrict__ idx)
{
    if (blockIdx.x >= NBLK_GLB) {
        // ------------------- middle rows (persistent) -------------------
        int lane = threadIdx.x & 31;
        int grp = lane >> 3;
        int d = lane & 7;
        int gw = (blockIdx.x - NBLK_GLB) * 8 + (threadIdx.x >> 5);   // 0..3551

        for (int base = gw * 4; base < N_ITEMS; base += MID_STRIDE) {
            int item = base + grp;

            int i = item % SMID;
            int h = (item / SMID) % NH;
            int b = item / (SMID * NH);
            int s = i + GG;

            const int2* ip = reinterpret_cast<const int2*>(idx + i * NIDX);
            int2 c0 = ip[0], c1 = ip[1], c2 = ip[2];
            int cols[NIDX] = {c0.x, c0.y, c1.x, c1.y, c2.x, c2.y};

            uint32_t rowq = ((unsigned)(b * SS + s) * DD + h * DK + d * 8) * 2;
            uint4 qv = *reinterpret_cast<const uint4*>(
                reinterpret_cast<const char*>(g_qp) + rowq);
            const __half2* q2 = reinterpret_cast<const __half2*>(&qv);

            uint4 kv[NIDX], vv[NIDX];
            #pragma unroll
            for (int j = 0; j < NIDX; j++) {
                uint32_t ro = ((unsigned)(b * SS + cols[j]) * DD + h * DK + d * 8) * 2;
                kv[j] = *reinterpret_cast<const uint4*>(
                    reinterpret_cast<const char*>(g_kp) + ro);
                vv[j] = *reinterpret_cast<const uint4*>(
                    reinterpret_cast<const char*>(g_vp) + ro);
            }

            float sc[NIDX];
            #pragma unroll
            for (int j = 0; j < NIDX; j++) {
                const __half2* k2 = reinterpret_cast<const __half2*>(&kv[j]);
                __half2 a2 = __hmul2(q2[0], k2[0]);
                a2 = __hfma2(q2[1], k2[1], a2);
                a2 = __hfma2(q2[2], k2[2], a2);
                a2 = __hfma2(q2[3], k2[3], a2);
                float2 pf = __half22float2(a2);
                float p = pf.x + pf.y;
                p += __shfl_xor_sync(0xFFFFFFFFu, p, 1);
                p += __shfl_xor_sync(0xFFFFFFFFu, p, 2);
                p += __shfl_xor_sync(0xFFFFFFFFu, p, 4);
                sc[j] = p;
            }

            // Dedupe: only possible duplicate is cols[j] == cols[0] (global 0 col).
            float denom = (float)SS;
            __half2 w2[NIDX];
            #pragma unroll
            for (int j = 0; j < NIDX; j++) {
                bool dup = (j > 0) && (cols[j] == cols[0]);
                float wv = dup ? 0.0f : (__expf(sc[j] * 0.125f) - 1.0f);
                denom += wv;
                w2[j] = __half2half2(__float2half_rn(wv));
            }

            __half2 corr[4];
            {
                const __half2* v2 = reinterpret_cast<const __half2*>(&vv[0]);
                #pragma unroll
                for (int e = 0; e < 4; e++) corr[e] = __hmul2(w2[0], v2[e]);
            }
            #pragma unroll
            for (int j = 1; j < NIDX; j++) {
                const __half2* v2 = reinterpret_cast<const __half2*>(&vv[j]);
                #pragma unroll
                for (int e = 0; e < 4; e++) corr[e] = __hfma2(w2[j], v2[e], corr[e]);
            }

            const float* vs = g_vsum + b * DD + h * DV + d * 8;
            float4 u0 = *reinterpret_cast<const float4*>(vs);
            float4 u1 = *reinterpret_cast<const float4*>(vs + 4);
            float inv = 1.0f / denom;
            float2 cf0 = __half22float2(corr[0]);
            float2 cf1 = __half22float2(corr[1]);
            float2 cf2 = __half22float2(corr[2]);
            float2 cf3 = __half22float2(corr[3]);
            float of[8] = {(u0.x + cf0.x) * inv, (u0.y + cf0.y) * inv,
                           (u0.z + cf1.x) * inv, (u0.w + cf1.y) * inv,
                           (u1.x + cf2.x) * inv, (u1.y + cf2.y) * inv,
                           (u1.z + cf3.x) * inv, (u1.w + cf3.y) * inv};

            __half2 hi[4], lo[4];
            #pragma unroll
            for (int e = 0; e < 4; e++) {
                __half h0 = __float2half(of[2 * e]);
                __half h1 = __float2half(of[2 * e + 1]);
                hi[e] = __halves2half2(h0, h1);
                lo[e] = __halves2half2(
                    __float2half(of[2 * e] - __half2float(h0)),
                    __float2half(of[2 * e + 1] - __half2float(h1)));
            }
            size_t obase = ((size_t)b * SS + s) * DD + h * DV + d * 8;
            *reinterpret_cast<uint4*>(g_ah + obase) = *reinterpret_cast<uint4*>(hi);
            *reinterpret_cast<uint4*>(g_al + obase) = *reinterpret_cast<uint4*>(lo);
        }
    } else {
        // ------------------- global rows -------------------
        int item = blockIdx.x;
        int r = item % 2;
        int h = (item / 2) % NH;
        int b = item / (2 * NH);
        int s = r ? (SS - 1) : 0;
        int tid = threadIdx.x;

        __shared__ float sc[SS];
        __shared__ float qs[DK];
        __shared__ float red[256];

        const __half* qrow = g_qp + ((size_t)b * SS + s) * DD + h * DK;
        if (tid < DK) qs[tid] = __half2float(qrow[tid]);
        __syncthreads();

        for (int t = tid; t < SS; t += 256) {
            const __half* krow = g_kp + ((size_t)b * SS + t) * DD + h * DK;
            float p = 0.0f;
            #pragma unroll
            for (int dd = 0; dd < DK; dd++) p = fmaf(qs[dd], __half2float(krow[dd]), p);
            sc[t] = p * 0.125f;
        }
        __syncthreads();

        float m = -1e30f;
        for (int t = tid; t < SS; t += 256) m = fmaxf(m, sc[t]);
        red[tid] = m; __syncthreads();
        for (int o = 128; o > 0; o >>= 1) {
            if (tid < o) red[tid] = fmaxf(red[tid], red[tid + o]);
            __syncthreads();
        }
        m = red[0];
        __syncthreads();

        float sum = 0.0f;
        for (int t = tid; t < SS; t += 256) {
            float e = __expf(sc[t] - m);
            sc[t] = e;
            sum += e;
        }
        red[tid] = sum; __syncthreads();
        for (int o = 128; o > 0; o >>= 1) {
            if (tid < o) red[tid] += red[tid + o];
            __syncthreads();
        }
        float inv = 1.0f / red[0];
        __syncthreads();

        int dv = tid % DV;
        int chunk = tid / DV;
        float acc = 0.0f;
        const __half* vb = g_vp + (size_t)b * SS * DD + h * DV + dv;
        for (int t = chunk * (SS / 4); t < (chunk + 1) * (SS / 4); t++)
            acc = fmaf(sc[t], __half2float(vb[(size_t)t * DD]), acc);
        red[tid] = acc; __syncthreads();
        if (tid < DV) {
            float o = (red[dv] + red[DV + dv] + red[2 * DV + dv] + red[3 * DV + dv]) * inv;
            store_hl(((size_t)b * SS + s) * DD + h * DV + dv, o);
        }
    }
}

// ---------------------------------------------------------------------------
extern "C" void kernel_launch(void* const* d_in, const int* in_sizes, int n_in,
                              void* d_out, int out_size)
{
    const float* Q  = (const float*)d_in[0];
    const float* K  = (const float*)d_in[1];
    const float* V  = (const float*)d_in[2];
    const float* Wq = (const float*)d_in[3];
    const float* Wk = (const float*)d_in[4];
    const float* Wv = (const float*)d_in[5];
    const float* Wo = (const float*)d_in[6];
    const int*   idx = (const int*)d_in[7];
    float* out = (float*)d_out;

    float* pvs;
    cudaGetSymbolAddress((void**)&pvs, g_vsum);

    __half *qp, *kp, *vp, *qh, *kh, *vh, *ah, *al;
    __half *wqh, *wkh, *wvh, *wvl, *woh, *wol;
    cudaGetSymbolAddress((void**)&qp, g_qp);
    cudaGetSymbolAddress((void**)&kp, g_kp);
    cudaGetSymbolAddress((void**)&vp, g_vp);
    cudaGetSymbolAddress((void**)&qh, g_qh);
    cudaGetSymbolAddress((void**)&kh, g_kh);
    cudaGetSymbolAddress((void**)&vh, g_vh);
    cudaGetSymbolAddress((void**)&ah, g_ah);  cudaGetSymbolAddress((void**)&al, g_al);
    cudaGetSymbolAddress((void**)&wqh, g_wqh);
    cudaGetSymbolAddress((void**)&wkh, g_wkh);
    cudaGetSymbolAddress((void**)&wvh, g_wvh); cudaGetSymbolAddress((void**)&wvl, g_wvl);
    cudaGetSymbolAddress((void**)&woh, g_woh); cudaGetSymbolAddress((void**)&wol, g_wol);

    constexpr int SMEM128 = NSTG * (2 * 128 * LDT * 2 + 2 * 128 * LDT * 2);
    cudaFuncSetAttribute(gemm_mma<128>, cudaFuncAttributeMaxDynamicSharedMemorySize, SMEM128);

    const int n4_big = MROWS * DD / 4;
    const int n4_w   = DD * DD / 4;
    const int bl_big = (n4_big + 255) / 256;
    const int bl_w   = (n4_w + 255) / 256;

    SplitN si;
    si.x[0] = (const float4*)Q; si.hi[0] = (ushort4*)qh; si.lo[0] = nullptr;
    si.x[1] = (const float4*)K; si.hi[1] = (ushort4*)kh; si.lo[1] = nullptr;
    si.x[2] = (const float4*)V; si.hi[2] = (ushort4*)vh; si.lo[2] = nullptr;
    si.x[3] = si.x[0]; si.hi[3] = si.hi[0]; si.lo[3] = nullptr;
    si.zero_vsum = 0;
    split_multi<<<dim3(bl_big, 3), 256>>>(si, n4_big);

    SplitN sw;
    sw.x[0] = (const float4*)Wq; sw.hi[0] = (ushort4*)wqh; sw.lo[0] = nullptr;
    sw.x[1] = (const float4*)Wk; sw.hi[1] = (ushort4*)wkh; sw.lo[1] = nullptr;
    sw.x[2] = (const float4*)Wv; sw.hi[2] = (ushort4*)wvh; sw.lo[2] = (ushort4*)wvl;
    sw.x[3] = (const float4*)Wo; sw.hi[3] = (ushort4*)woh; sw.lo[3] = (ushort4*)wol;
    sw.zero_vsum = 1;
    split_multi<<<dim3(bl_w, 4), 256>>>(sw, n4_w);

    Gemm3 g3;
    g3.g[0] = {vh, nullptr, wvh, wvl, nullptr, vp, pvs, 2};
    g3.g[1] = {qh, nullptr, wqh, nullptr, nullptr, qp, nullptr, 1};
    g3.g[2] = {kh, nullptr, wkh, nullptr, nullptr, kp, nullptr, 1};
    gemm_mma<128><<<dim3(DD / 128, MROWS / BM, 3), 256, SMEM128>>>(g3);

    attn_kernel<<<NBLK_GLB + NBLK_MID, 256>>>(idx);

    // O GEMM: BNT=128, nprod=3 — 192 CTAs = single wave at 2 CTAs/SM.
    Gemm3 go;
    go.g[0] = {ah, al, woh, wol, out, nullptr, nullptr, 3};
    go.g[1] = go.g[0];
    go.g[2] = go.g[0];
    gemm_mma<128><<<dim3(DD / 128, MROWS / BM, 1), 256, SMEM128>>>(go);
}

// round 15
// speedup vs baseline: 1.4485x; 1.2478x over previous
#include <cuda_runtime.h>
#include <cuda_fp16.h>
#include <cstdint>
#include <math.h>

// Problem constants
#define BB 2
#define SS 2048
#define DD 768
#define NH 12
#define DK 64
#define DV 64
#define GG 1
#define NIDX 6
#define SMID (SS - 2*GG)
#define MROWS (BB * SS)

// GEMM tiling
#define BM 128
#define BKK 32
#define NCHK (DD / BKK)
#define LDT 40
#define NSTG 2

// Fused attention kernel geometry: global blocks FIRST, then persistent mid.
#define N_ITEMS (BB * NH * SMID)                  // 49104 (divisible by 4)
#define NBLK_MID 444                              // 148 SMs x 3 CTAs
#define NBLK_GLB (BB * NH * 2)                    // 48
#define MID_STRIDE (NBLK_MID * 8 * 4)             // items per loop round = 14208

// ---------------------------------------------------------------------------
// Scratch
// ---------------------------------------------------------------------------
__device__ float g_vsum[BB * DD];

__device__ __half g_qp[MROWS * DD];
__device__ __half g_kp[MROWS * DD];
__device__ __half g_vp[MROWS * DD];
__device__ __half g_qh[MROWS * DD];
__device__ __half g_kh[MROWS * DD];
__device__ __half g_vh[MROWS * DD];
__device__ __half g_ah[MROWS * DD], g_al[MROWS * DD];
__device__ __half g_wqh[DD * DD];
__device__ __half g_wkh[DD * DD];
__device__ __half g_wvh[DD * DD], g_wvl[DD * DD];
__device__ __half g_woh[DD * DD], g_wol[DD * DD];

// ---------------------------------------------------------------------------
// PTX helpers (portable sm_80+ ISA)
// ---------------------------------------------------------------------------
__device__ __forceinline__ uint32_t smem_u32(const void* p) {
    uint32_t a;
    asm("{ .reg .u64 t; cvta.to.shared.u64 t, %1; cvt.u32.u64 %0, t; }"
        : "=r"(a) : "l"(p));
    return a;
}
__device__ __forceinline__ void cp_async16(uint32_t dst, const void* src) {
    asm volatile("cp.async.cg.shared.global [%0], [%1], 16;"
                 :: "r"(dst), "l"(src) : "memory");
}
__device__ __forceinline__ void cp_commit() {
    asm volatile("cp.async.commit_group;" ::: "memory");
}
template <int N>
__device__ __forceinline__ void cp_wait() {
    asm volatile("cp.async.wait_group %0;" :: "n"(N) : "memory");
}
__device__ __forceinline__ void ldm4(uint32_t* r, uint32_t addr) {
    asm volatile("ldmatrix.sync.aligned.m8n8.x4.shared.b16 {%0,%1,%2,%3}, [%4];"
                 : "=r"(r[0]), "=r"(r[1]), "=r"(r[2]), "=r"(r[3]) : "r"(addr));
}
__device__ __forceinline__ void mma16816(float* c, const uint32_t* a, const uint32_t* b) {
    asm volatile(
        "mma.sync.aligned.m16n8k16.row.col.f32.f16.f16.f32 "
        "{%0,%1,%2,%3}, {%4,%5,%6,%7}, {%8,%9}, {%0,%1,%2,%3};"
        : "+f"(c[0]), "+f"(c[1]), "+f"(c[2]), "+f"(c[3])
        : "r"(a[0]), "r"(a[1]), "r"(a[2]), "r"(a[3]), "r"(b[0]), "r"(b[1]));
}

struct GemmArgs {
    const __half *Ah, *Al, *Bh, *Bl;
    float* C;
    __half* Ch;
    float* vsum;
    int nprod;        // 1: Ah*Bh ; 2: + Ah*Bl ; 3: + Al*Bh
};
struct Gemm3 { GemmArgs g[3]; };

// ---------------------------------------------------------------------------
// GEMM (unchanged)
// ---------------------------------------------------------------------------
template <int BNT>
__global__ __launch_bounds__(256, 2) void gemm_mma(Gemm3 ga)
{
    constexpr int WNT = BNT / 4;
    constexpr int NJ = WNT / 8;
    constexpr int TILEB_A = 128 * LDT * 2;
    constexpr int TILEB_B = BNT * LDT * 2;
    constexpr int STAGEB = 2 * TILEB_A + 2 * TILEB_B;
    constexpr int NCHUNK = (2 * 128 + 2 * BNT) * 4;
    constexpr int PER_THR = NCHUNK / 256;

    extern __shared__ char smem[];
    const GemmArgs& A = ga.g[blockIdx.z];
    const int nprod = A.nprod;
    const uint32_t sb = smem_u32(smem);
    const int tid = threadIdx.x;
    const int wid = tid >> 5;
    const int lane = tid & 31;
    const int bm = blockIdx.y * BM;
    const int bn = blockIdx.x * BNT;
    const int wm = (wid >> 2) * 64;
    const int wn = (wid & 3) * WNT;

    float acc[4][NJ][4];
    #pragma unroll
    for (int i = 0; i < 4; i++)
        #pragma unroll
        for (int j = 0; j < NJ; j++)
            #pragma unroll
            for (int e = 0; e < 4; e++) acc[i][j][e] = 0.0f;

    auto issue = [&](int kt) {
        const int st = kt % NSTG;
        #pragma unroll
        for (int q8 = 0; q8 < PER_THR; q8++) {
            int q = tid + q8 * 256;
            if (q < 1024) {
                int t = q >> 9;
                if (t == 1 && nprod < 3) continue;
                int r = (q >> 2) & 127;
                int c = q & 3;
                const __half* src = (t ? A.Al : A.Ah)
                                    + (size_t)(bm + r) * DD + kt * BKK + c * 8;
                uint32_t dst = sb + st * STAGEB + t * TILEB_A + r * (LDT * 2) + c * 16;
                cp_async16(dst, src);
            } else {
                int q2 = q - 1024;
                int t = q2 / (BNT * 4);
                if (t == 1 && nprod < 2) continue;
                int r = (q2 >> 2) % BNT;
                int c = q2 & 3;
                const __half* src = (t ? A.Bl : A.Bh)
                                    + (size_t)(bn + r) * DD + kt * BKK + c * 8;
                uint32_t dst = sb + st * STAGEB + 2 * TILEB_A + t * TILEB_B
                             + r * (LDT * 2) + c * 16;
                cp_async16(dst, src);
            }
        }
        cp_commit();
    };

    const int a_row = lane & 15;
    const int a_col = (lane >> 4) * 8;
    const int b_row = (lane & 7) + ((lane >> 4) << 3);
    const int b_col = ((lane >> 3) & 1) * 8;

    auto compute = [&](int kt) {
        const uint32_t base = sb + (kt % NSTG) * STAGEB;
        #pragma unroll
        for (int ks = 0; ks < 2; ks++) {
            const int k0 = ks * 16;
            uint32_t bh[NJ / 2][4], bl[NJ / 2][4];
            #pragma unroll
            for (int nh = 0; nh < NJ / 2; nh++) {
                uint32_t off = (uint32_t)(wn + nh * 16 + b_row) * (LDT * 2)
                             + (k0 + b_col) * 2;
                ldm4(bh[nh], base + 2 * TILEB_A + off);
                if (nprod >= 2)
                    ldm4(bl[nh], base + 2 * TILEB_A + TILEB_B + off);
            }
            uint32_t af[4][4];
            #pragma unroll
            for (int mt = 0; mt < 4; mt++) {
                uint32_t off = (uint32_t)(wm + mt * 16 + a_row) * (LDT * 2)
                             + (k0 + a_col) * 2;
                ldm4(af[mt], base + off);
            }
            if constexpr (NJ == 2) {
                uint32_t alf[4][4];
                if (nprod >= 3) {
                    #pragma unroll
                    for (int mt = 0; mt < 4; mt++) {
                        uint32_t off = (uint32_t)(wm + mt * 16 + a_row) * (LDT * 2)
                                     + (k0 + a_col) * 2;
                        ldm4(alf[mt], base + TILEB_A + off);
                    }
                }
                #pragma unroll
                for (int mt = 0; mt < 4; mt++)
                    #pragma unroll
                    for (int j = 0; j < NJ; j++) {
                        mma16816(acc[mt][j], af[mt], &bh[j >> 1][(j & 1) * 2]);
                        if (nprod >= 2)
                            mma16816(acc[mt][j], af[mt], &bl[j >> 1][(j & 1) * 2]);
                        if (nprod >= 3)
                            mma16816(acc[mt][j], alf[mt], &bh[j >> 1][(j & 1) * 2]);
                    }
            } else {
                #pragma unroll
                for (int mt = 0; mt < 4; mt++)
                    #pragma unroll
                    for (int j = 0; j < NJ; j++) {
                        mma16816(acc[mt][j], af[mt], &bh[j >> 1][(j & 1) * 2]);
                        if (nprod >= 2)
                            mma16816(acc[mt][j], af[mt], &bl[j >> 1][(j & 1) * 2]);
                    }
                if (nprod >= 3) {
                    #pragma unroll
                    for (int mt = 0; mt < 4; mt++) {
                        uint32_t off = (uint32_t)(wm + mt * 16 + a_row) * (LDT * 2)
                                     + (k0 + a_col) * 2;
                        ldm4(af[mt], base + TILEB_A + off);
                    }
                    #pragma unroll
                    for (int mt = 0; mt < 4; mt++)
                        #pragma unroll
                        for (int j = 0; j < NJ; j++)
                            mma16816(acc[mt][j], af[mt], &bh[j >> 1][(j & 1) * 2]);
                }
            }
        }
    };

    issue(0);
    for (int kt = 0; kt < NCHK; kt++) {
        cp_wait<0>();
        __syncthreads();
        if (kt + 1 < NCHK) issue(kt + 1);
        compute(kt);
    }

    if (A.Ch) {
        #pragma unroll
        for (int mt = 0; mt < 4; mt++) {
            #pragma unroll
            for (int j = 0; j < NJ; j++) {
                int row = bm + wm + mt * 16 + (lane >> 2);
                int col = bn + wn + j * 8 + (lane & 3) * 2;
                *reinterpret_cast<__half2*>(A.Ch + (size_t)row * DD + col)
                    = __floats2half2_rn(acc[mt][j][0], acc[mt][j][1]);
                *reinterpret_cast<__half2*>(A.Ch + (size_t)(row + 8) * DD + col)
                    = __floats2half2_rn(acc[mt][j][2], acc[mt][j][3]);
            }
        }
    } else {
        #pragma unroll
        for (int mt = 0; mt < 4; mt++) {
            #pragma unroll
            for (int j = 0; j < NJ; j++) {
                int row = bm + wm + mt * 16 + (lane >> 2);
                int col = bn + wn + j * 8 + (lane & 3) * 2;
                *reinterpret_cast<float2*>(A.C + (size_t)row * DD + col)
                    = make_float2(acc[mt][j][0], acc[mt][j][1]);
                *reinterpret_cast<float2*>(A.C + (size_t)(row + 8) * DD + col)
                    = make_float2(acc[mt][j][2], acc[mt][j][3]);
            }
        }
    }

    if (A.vsum) {
        int b = bm / SS;
        #pragma unroll
        for (int j = 0; j < NJ; j++) {
            float s0 = 0.0f, s1 = 0.0f;
            #pragma unroll
            for (int mt = 0; mt < 4; mt++) {
                s0 += acc[mt][j][0] + acc[mt][j][2];
                s1 += acc[mt][j][1] + acc[mt][j][3];
            }
            #pragma unroll
            for (int o = 4; o < 32; o <<= 1) {
                s0 += __shfl_xor_sync(0xFFFFFFFFu, s0, o);
                s1 += __shfl_xor_sync(0xFFFFFFFFu, s1, o);
            }
            if (lane < 4) {
                int col = bn + wn + j * 8 + lane * 2;
                atomicAdd(&A.vsum[b * DD + col], s0);
                atomicAdd(&A.vsum[b * DD + col + 1], s1);
            }
        }
    }
}

// ---------------------------------------------------------------------------
// fp32 -> (f16 hi, f16 lo) splits
// ---------------------------------------------------------------------------
__device__ __forceinline__ void split4h(float4 v, ushort4& h, ushort4& l) {
    __half b;
    b = __float2half(v.x); h.x = __half_as_ushort(b);
    l.x = __half_as_ushort(__float2half(v.x - __half2float(b)));
    b = __float2half(v.y); h.y = __half_as_ushort(b);
    l.y = __half_as_ushort(__float2half(v.y - __half2float(b)));
    b = __float2half(v.z); h.z = __half_as_ushort(b);
    l.z = __half_as_ushort(__float2half(v.z - __half2float(b)));
    b = __float2half(v.w); h.w = __half_as_ushort(b);
    l.w = __half_as_ushort(__float2half(v.w - __half2float(b)));
}

struct SplitN {
    const float4* x[4];
    ushort4* hi[4];
    ushort4* lo[4];
    int zero_vsum;
};
__global__ void split_multi(SplitN a, int n4)
{
    int w = blockIdx.y;
    int i = blockIdx.x * blockDim.x + threadIdx.x;
    if (a.zero_vsum && w == 0 && i < BB * DD) g_vsum[i] = 0.0f;
    if (i >= n4) return;
    ushort4 h, l;
    split4h(a.x[w][i], h, l);
    a.hi[w][i] = h;
    if (a.lo[w]) a.lo[w][i] = l;
}

// ---------------------------------------------------------------------------
// Fused attention. Blocks [0,NBLK_GLB): global rows (now coalesced score
// phase). Then NBLK_MID persistent mid blocks (8 lanes/item, 4 items/warp).
// ---------------------------------------------------------------------------
__device__ __forceinline__ void store_hl(size_t off, float v) {
    __half h = __float2half(v);
    g_ah[off] = h;
    g_al[off] = __float2half(v - __half2float(h));
}

__global__ __launch_bounds__(256, 3) void attn_kernel(const int* __restrict__ idx)
{
    if (blockIdx.x >= NBLK_GLB) {
        // ------------------- middle rows (persistent) -------------------
        int lane = threadIdx.x & 31;
        int grp = lane >> 3;
        int d = lane & 7;
        int gw = (blockIdx.x - NBLK_GLB) * 8 + (threadIdx.x >> 5);

        for (int base = gw * 4; base < N_ITEMS; base += MID_STRIDE) {
            int item = base + grp;

            int i = item % SMID;
            int h = (item / SMID) % NH;
            int b = item / (SMID * NH);
            int s = i + GG;

            const int2* ip = reinterpret_cast<const int2*>(idx + i * NIDX);
            int2 c0 = ip[0], c1 = ip[1], c2 = ip[2];
            int cols[NIDX] = {c0.x, c0.y, c1.x, c1.y, c2.x, c2.y};

            uint32_t rowq = ((unsigned)(b * SS + s) * DD + h * DK + d * 8) * 2;
            uint4 qv = *reinterpret_cast<const uint4*>(
                reinterpret_cast<const char*>(g_qp) + rowq);
            const __half2* q2 = reinterpret_cast<const __half2*>(&qv);

            uint4 kv[NIDX], vv[NIDX];
            #pragma unroll
            for (int j = 0; j < NIDX; j++) {
                uint32_t ro = ((unsigned)(b * SS + cols[j]) * DD + h * DK + d * 8) * 2;
                kv[j] = *reinterpret_cast<const uint4*>(
                    reinterpret_cast<const char*>(g_kp) + ro);
                vv[j] = *reinterpret_cast<const uint4*>(
                    reinterpret_cast<const char*>(g_vp) + ro);
            }

            float sc[NIDX];
            #pragma unroll
            for (int j = 0; j < NIDX; j++) {
                const __half2* k2 = reinterpret_cast<const __half2*>(&kv[j]);
                __half2 a2 = __hmul2(q2[0], k2[0]);
                a2 = __hfma2(q2[1], k2[1], a2);
                a2 = __hfma2(q2[2], k2[2], a2);
                a2 = __hfma2(q2[3], k2[3], a2);
                float2 pf = __half22float2(a2);
                float p = pf.x + pf.y;
                p += __shfl_xor_sync(0xFFFFFFFFu, p, 1);
                p += __shfl_xor_sync(0xFFFFFFFFu, p, 2);
                p += __shfl_xor_sync(0xFFFFFFFFu, p, 4);
                sc[j] = p;
            }

            float denom = (float)SS;
            __half2 w2[NIDX];
            #pragma unroll
            for (int j = 0; j < NIDX; j++) {
                bool dup = (j > 0) && (cols[j] == cols[0]);
                float wv = dup ? 0.0f : (__expf(sc[j] * 0.125f) - 1.0f);
                denom += wv;
                w2[j] = __half2half2(__float2half_rn(wv));
            }

            __half2 corr[4];
            {
                const __half2* v2 = reinterpret_cast<const __half2*>(&vv[0]);
                #pragma unroll
                for (int e = 0; e < 4; e++) corr[e] = __hmul2(w2[0], v2[e]);
            }
            #pragma unroll
            for (int j = 1; j < NIDX; j++) {
                const __half2* v2 = reinterpret_cast<const __half2*>(&vv[j]);
                #pragma unroll
                for (int e = 0; e < 4; e++) corr[e] = __hfma2(w2[j], v2[e], corr[e]);
            }

            const float* vs = g_vsum + b * DD + h * DV + d * 8;
            float4 u0 = *reinterpret_cast<const float4*>(vs);
            float4 u1 = *reinterpret_cast<const float4*>(vs + 4);
            float inv = 1.0f / denom;
            float2 cf0 = __half22float2(corr[0]);
            float2 cf1 = __half22float2(corr[1]);
            float2 cf2 = __half22float2(corr[2]);
            float2 cf3 = __half22float2(corr[3]);
            float of[8] = {(u0.x + cf0.x) * inv, (u0.y + cf0.y) * inv,
                           (u0.z + cf1.x) * inv, (u0.w + cf1.y) * inv,
                           (u1.x + cf2.x) * inv, (u1.y + cf2.y) * inv,
                           (u1.z + cf3.x) * inv, (u1.w + cf3.y) * inv};

            __half2 hi[4], lo[4];
            #pragma unroll
            for (int e = 0; e < 4; e++) {
                __half h0 = __float2half(of[2 * e]);
                __half h1 = __float2half(of[2 * e + 1]);
                hi[e] = __halves2half2(h0, h1);
                lo[e] = __halves2half2(
                    __float2half(of[2 * e] - __half2float(h0)),
                    __float2half(of[2 * e + 1] - __half2float(h1)));
            }
            size_t obase = ((size_t)b * SS + s) * DD + h * DV + d * 8;
            *reinterpret_cast<uint4*>(g_ah + obase) = *reinterpret_cast<uint4*>(hi);
            *reinterpret_cast<uint4*>(g_al + obase) = *reinterpret_cast<uint4*>(lo);
        }
    } else {
        // ------------------- global rows (coalesced) -------------------
        int item = blockIdx.x;
        int r = item % 2;
        int h = (item / 2) % NH;
        int b = item / (2 * NH);
        int s = r ? (SS - 1) : 0;
        int tid = threadIdx.x;
        int warp = tid >> 5;
        int lane = tid & 31;
        int grp = lane >> 3;      // token within warp group of 4
        int d = lane & 7;         // 8-half slice of the 64-dim row

        __shared__ float sc[SS];
        __shared__ float red[256];

        // q slice in registers (half2 x4)
        uint32_t rowq = ((unsigned)(b * SS + s) * DD + h * DK + d * 8) * 2;
        uint4 qv = *reinterpret_cast<const uint4*>(
            reinterpret_cast<const char*>(g_qp) + rowq);
        const __half2* q2 = reinterpret_cast<const __half2*>(&qv);

        // Scores: 4 tokens per warp per iteration, coalesced 16B loads.
        const char* kbase = reinterpret_cast<const char*>(g_kp)
                          + ((unsigned)(b * SS) * DD + h * DK + d * 8) * 2;
        for (int t = warp * 4 + grp; t < SS; t += 32) {
            uint4 kvv = *reinterpret_cast<const uint4*>(kbase + (unsigned)t * (DD * 2));
            const __half2* k2 = reinterpret_cast<const __half2*>(&kvv);
            __half2 a2 = __hmul2(q2[0], k2[0]);
            a2 = __hfma2(q2[1], k2[1], a2);
            a2 = __hfma2(q2[2], k2[2], a2);
            a2 = __hfma2(q2[3], k2[3], a2);
            float2 pf = __half22float2(a2);
            float p = pf.x + pf.y;
            p += __shfl_xor_sync(0xFFFFFFFFu, p, 1);
            p += __shfl_xor_sync(0xFFFFFFFFu, p, 2);
            p += __shfl_xor_sync(0xFFFFFFFFu, p, 4);
            if (d == 0) sc[t] = p * 0.125f;
        }
        __syncthreads();

        float m = -1e30f;
        for (int t = tid; t < SS; t += 256) m = fmaxf(m, sc[t]);
        red[tid] = m; __syncthreads();
        for (int o = 128; o > 0; o >>= 1) {
            if (tid < o) red[tid] = fmaxf(red[tid], red[tid + o]);
            __syncthreads();
        }
        m = red[0];
        __syncthreads();

        float sum = 0.0f;
        for (int t = tid; t < SS; t += 256) {
            float e = __expf(sc[t] - m);
            sc[t] = e;
            sum += e;
        }
        red[tid] = sum; __syncthreads();
        for (int o = 128; o > 0; o >>= 1) {
            if (tid < o) red[tid] += red[tid + o];
            __syncthreads();
        }
        float inv = 1.0f / red[0];
        __syncthreads();

        int dv = tid % DV;
        int chunk = tid / DV;
        float acc = 0.0f;
        const __half* vb = g_vp + (size_t)b * SS * DD + h * DV + dv;
        for (int t = chunk * (SS / 4); t < (chunk + 1) * (SS / 4); t++)
            acc = fmaf(sc[t], __half2float(vb[(size_t)t * DD]), acc);
        red[tid] = acc; __syncthreads();
        if (tid < DV) {
            float o = (red[dv] + red[DV + dv] + red[2 * DV + dv] + red[3 * DV + dv]) * inv;
            store_hl(((size_t)b * SS + s) * DD + h * DV + dv, o);
        }
    }
}

// ---------------------------------------------------------------------------
extern "C" void kernel_launch(void* const* d_in, const int* in_sizes, int n_in,
                              void* d_out, int out_size)
{
    const float* Q  = (const float*)d_in[0];
    const float* K  = (const float*)d_in[1];
    const float* V  = (const float*)d_in[2];
    const float* Wq = (const float*)d_in[3];
    const float* Wk = (const float*)d_in[4];
    const float* Wv = (const float*)d_in[5];
    const float* Wo = (const float*)d_in[6];
    const int*   idx = (const int*)d_in[7];
    float* out = (float*)d_out;

    float* pvs;
    cudaGetSymbolAddress((void**)&pvs, g_vsum);

    __half *qp, *kp, *vp, *qh, *kh, *vh, *ah, *al;
    __half *wqh, *wkh, *wvh, *wvl, *woh, *wol;
    cudaGetSymbolAddress((void**)&qp, g_qp);
    cudaGetSymbolAddress((void**)&kp, g_kp);
    cudaGetSymbolAddress((void**)&vp, g_vp);
    cudaGetSymbolAddress((void**)&qh, g_qh);
    cudaGetSymbolAddress((void**)&kh, g_kh);
    cudaGetSymbolAddress((void**)&vh, g_vh);
    cudaGetSymbolAddress((void**)&ah, g_ah);  cudaGetSymbolAddress((void**)&al, g_al);
    cudaGetSymbolAddress((void**)&wqh, g_wqh);
    cudaGetSymbolAddress((void**)&wkh, g_wkh);
    cudaGetSymbolAddress((void**)&wvh, g_wvh); cudaGetSymbolAddress((void**)&wvl, g_wvl);
    cudaGetSymbolAddress((void**)&woh, g_woh); cudaGetSymbolAddress((void**)&wol, g_wol);

    constexpr int SMEM128 = NSTG * (2 * 128 * LDT * 2 + 2 * 128 * LDT * 2);
    cudaFuncSetAttribute(gemm_mma<128>, cudaFuncAttributeMaxDynamicSharedMemorySize, SMEM128);

    const int n4_big = MROWS * DD / 4;
    const int n4_w   = DD * DD / 4;
    const int bl_big = (n4_big + 255) / 256;
    const int bl_w   = (n4_w + 255) / 256;

    SplitN si;
    si.x[0] = (const float4*)Q; si.hi[0] = (ushort4*)qh; si.lo[0] = nullptr;
    si.x[1] = (const float4*)K; si.hi[1] = (ushort4*)kh; si.lo[1] = nullptr;
    si.x[2] = (const float4*)V; si.hi[2] = (ushort4*)vh; si.lo[2] = nullptr;
    si.x[3] = si.x[0]; si.hi[3] = si.hi[0]; si.lo[3] = nullptr;
    si.zero_vsum = 0;
    split_multi<<<dim3(bl_big, 3), 256>>>(si, n4_big);

    SplitN sw;
    sw.x[0] = (const float4*)Wq; sw.hi[0] = (ushort4*)wqh; sw.lo[0] = nullptr;
    sw.x[1] = (const float4*)Wk; sw.hi[1] = (ushort4*)wkh; sw.lo[1] = nullptr;
    sw.x[2] = (const float4*)Wv; sw.hi[2] = (ushort4*)wvh; sw.lo[2] = (ushort4*)wvl;
    sw.x[3] = (const float4*)Wo; sw.hi[3] = (ushort4*)woh; sw.lo[3] = (ushort4*)wol;
    sw.zero_vsum = 1;
    split_multi<<<dim3(bl_w, 4), 256>>>(sw, n4_w);

    Gemm3 g3;
    g3.g[0] = {vh, nullptr, wvh, wvl, nullptr, vp, pvs, 2};
    g3.g[1] = {qh, nullptr, wqh, nullptr, nullptr, qp, nullptr, 1};
    g3.g[2] = {kh, nullptr, wkh, nullptr, nullptr, kp, nullptr, 1};
    gemm_mma<128><<<dim3(DD / 128, MROWS / BM, 3), 256, SMEM128>>>(g3);

    attn_kernel<<<NBLK_GLB + NBLK_MID, 256>>>(idx);

    Gemm3 go;
    go.g[0] = {ah, al, woh, wol, out, nullptr, nullptr, 3};
    go.g[1] = go.g[0];
    go.g[2] = go.g[0];
    gemm_mma<128><<<dim3(DD / 128, MROWS / BM, 1), 256, SMEM128>>>(go);
}